// round 6
// baseline (speedup 1.0000x reference)
#include <cuda_runtime.h>
#include <cuda_bf16.h>
#include <cstdint>

#define SEQ   2048
#define DM    1024
#define NH    16
#define DEP   64
#define MTOT  4096
#define BH    32
#define NTHR  512

// ---------------------------------------------------------------------------
// Device scratch (allocation-free)
// ---------------------------------------------------------------------------
__device__ __nv_bfloat16 g_wq_hi[DM*DM], g_wq_lo[DM*DM];
__device__ __nv_bfloat16 g_wk_hi[DM*DM], g_wk_lo[DM*DM];
__device__ __nv_bfloat16 g_wv_hi[DM*DM], g_wv_lo[DM*DM];
__device__ __nv_bfloat16 g_wo_hi[DM*DM], g_wo_lo[DM*DM];
__device__ __nv_bfloat16 g_qh_hi[BH*SEQ*DEP], g_qh_lo[BH*SEQ*DEP];
__device__ __nv_bfloat16 g_kh_hi[BH*SEQ*DEP], g_kh_lo[BH*SEQ*DEP];
__device__ __nv_bfloat16 g_vt_hi[BH*DEP*SEQ], g_vt_lo[BH*DEP*SEQ];
__device__ __nv_bfloat16 g_at_hi[MTOT*DM],    g_at_lo[MTOT*DM];
__device__ float g_pmax[BH*16*SEQ], g_psum[BH*16*SEQ];
__device__ float g_M[BH*SEQ], g_invZ[BH*SEQ];

// ---------------------------------------------------------------------------
// Helpers
// ---------------------------------------------------------------------------
__device__ __forceinline__ uint32_t smem_u32(const void* p) {
    uint32_t a;
    asm("{ .reg .u64 t; cvta.to.shared.u64 t, %1; cvt.u32.u64 %0, t; }"
        : "=r"(a) : "l"(p));
    return a;
}
#define CP16(s, g)  asm volatile("cp.async.cg.shared.global [%0], [%1], 16;" :: "r"(s), "l"(g))
#define CP_COMMIT() asm volatile("cp.async.commit_group;" ::: "memory")
#define CP_WAIT(n)  asm volatile("cp.async.wait_group %0;" :: "n"(n) : "memory")

#define LDSM4(R, addr) \
    asm volatile("ldmatrix.sync.aligned.m8n8.x4.shared.b16 {%0,%1,%2,%3}, [%4];" \
        : "=r"((R)[0]), "=r"((R)[1]), "=r"((R)[2]), "=r"((R)[3]) : "r"(addr))

#define MMA16816(d, a, b) \
    asm volatile("mma.sync.aligned.m16n8k16.row.col.f32.bf16.bf16.f32 " \
        "{%0,%1,%2,%3}, {%4,%5,%6,%7}, {%8,%9}, {%0,%1,%2,%3};" \
        : "+f"((d)[0]), "+f"((d)[1]), "+f"((d)[2]), "+f"((d)[3]) \
        : "r"((a)[0]), "r"((a)[1]), "r"((a)[2]), "r"((a)[3]), "r"((b)[0]), "r"((b)[1]))

__device__ __forceinline__ uint32_t swz(uint32_t b) { return b ^ ((b >> 3) & 0x70); }

__device__ __forceinline__ uint32_t pack_bf2(float x, float y) {
    __nv_bfloat162 t;
    t.x = __float2bfloat16(x);
    t.y = __float2bfloat16(y);
    return *(uint32_t*)&t;
}

__device__ __forceinline__ void lane_sw(int lane, uint32_t* a_sw, uint32_t* b_sw) {
    #pragma unroll
    for (int kk = 0; kk < 4; kk++) {
        a_sw[kk] = swz(((uint32_t)(lane & 15) << 7) + kk * 32 + ((uint32_t)(lane >> 4) << 4));
        b_sw[kk] = swz((((uint32_t)((lane & 7) | ((lane >> 4) << 3))) << 7)
                       + kk * 32 + (((uint32_t)(lane >> 3) & 1) << 4));
    }
}

// 64-wide K chunk, 3-term split-bf16 MMA
template<int MF, int NF>
__device__ __forceinline__ void compute_chunk(
    uint32_t AH, uint32_t AL, uint32_t BHb, uint32_t BLb,
    int warpM, int warpN, const uint32_t* a_sw, const uint32_t* b_sw,
    float (*acc)[NF][4])
{
    #pragma unroll
    for (int kk = 0; kk < 4; kk++) {
        uint32_t ah[MF][4], al[MF][4], bh[NF][2], bl[NF][2];
        #pragma unroll
        for (int mf = 0; mf < MF; mf++) {
            const uint32_t ro = (uint32_t)(warpM + mf * 16) * 128;
            LDSM4(ah[mf], AH + ro + a_sw[kk]);
            LDSM4(al[mf], AL + ro + a_sw[kk]);
        }
        #pragma unroll
        for (int p = 0; p < NF / 2; p++) {
            const uint32_t ro = (uint32_t)(warpN + p * 16) * 128;
            uint32_t t[4];
            LDSM4(t, BHb + ro + b_sw[kk]);
            bh[2*p][0] = t[0]; bh[2*p][1] = t[1];
            bh[2*p+1][0] = t[2]; bh[2*p+1][1] = t[3];
            LDSM4(t, BLb + ro + b_sw[kk]);
            bl[2*p][0] = t[0]; bl[2*p][1] = t[1];
            bl[2*p+1][0] = t[2]; bl[2*p+1][1] = t[3];
        }
        #pragma unroll
        for (int mf = 0; mf < MF; mf++)
            #pragma unroll
            for (int nf = 0; nf < NF; nf++) {
                MMA16816(acc[mf][nf], ah[mf], bh[nf]);
                MMA16816(acc[mf][nf], ah[mf], bl[nf]);
                MMA16816(acc[mf][nf], al[mf], bh[nf]);
            }
    }
}

// ---------------------------------------------------------------------------
// W[k][n] fp32 -> Wt[n][k] bf16 hi/lo; 4 matrices via z
// ---------------------------------------------------------------------------
__global__ void transpose_split_kernel(
    const float* W0, const float* W1, const float* W2, const float* W3,
    __nv_bfloat16* h0, __nv_bfloat16* h1, __nv_bfloat16* h2, __nv_bfloat16* h3,
    __nv_bfloat16* l0, __nv_bfloat16* l1, __nv_bfloat16* l2, __nv_bfloat16* l3)
{
    const float* Ws[4] = {W0, W1, W2, W3};
    __nv_bfloat16* hs[4] = {h0, h1, h2, h3};
    __nv_bfloat16* ls[4] = {l0, l1, l2, l3};
    const int z = blockIdx.z;
    const float* W = Ws[z];
    __nv_bfloat16* hi = hs[z];
    __nv_bfloat16* lo = ls[z];

    __shared__ float s[32][33];
    const int bx = blockIdx.x * 32, by = blockIdx.y * 32;
    const int tx = threadIdx.x, ty = threadIdx.y;  // 32 x 8
    #pragma unroll
    for (int j = 0; j < 4; j++)
        s[ty + j * 8][tx] = W[(size_t)(by + ty + j * 8) * DM + bx + tx];
    __syncthreads();
    #pragma unroll
    for (int j = 0; j < 4; j++) {
        int n = bx + ty + j * 8, k = by + tx;
        float v = s[tx][ty + j * 8];
        __nv_bfloat16 h = __float2bfloat16(v);
        hi[(size_t)n * DM + k] = h;
        lo[(size_t)n * DM + k] = __float2bfloat16(v - __bfloat162float(h));
    }
}

// ---------------------------------------------------------------------------
// Projections: A fp32 (q/k/v selected by z), B pre-split. CTA 128x128, 512 thr.
// ---------------------------------------------------------------------------
__global__ void __launch_bounds__(NTHR, 1)
gemm_proj(const float* __restrict__ qp, const float* __restrict__ kp,
          const float* __restrict__ vp,
          const __nv_bfloat16* __restrict__ wqh, const __nv_bfloat16* __restrict__ wkh,
          const __nv_bfloat16* __restrict__ wvh,
          const __nv_bfloat16* __restrict__ wql, const __nv_bfloat16* __restrict__ wkl,
          const __nv_bfloat16* __restrict__ wvl,
          const float* __restrict__ bqp, const float* __restrict__ bkp,
          const float* __restrict__ bvp,
          __nv_bfloat16* __restrict__ qhh, __nv_bfloat16* __restrict__ khh,
          __nv_bfloat16* __restrict__ vth,
          __nv_bfloat16* __restrict__ qhl, __nv_bfloat16* __restrict__ khl,
          __nv_bfloat16* __restrict__ vtl)
{
    extern __shared__ char smem[];
    const uint32_t sb = smem_u32(smem);
    const int tid = threadIdx.x, lane = tid & 31, wid = tid >> 5;
    const int bn = blockIdx.x * 128, bm = blockIdx.y * 128, z = blockIdx.z;

    const float* Aps[3] = {qp, kp, vp};
    const __nv_bfloat16* Bhs[3] = {wqh, wkh, wvh};
    const __nv_bfloat16* Bls[3] = {wql, wkl, wvl};
    const float* bias_s[3] = {bqp, bkp, bvp};
    __nv_bfloat16* ohs[3] = {qhh, khh, vth};
    __nv_bfloat16* ols[3] = {qhl, khl, vtl};
    const float* Ap = Aps[z];
    const __nv_bfloat16* Bh = Bhs[z];
    const __nv_bfloat16* Bl = Bls[z];
    const float* bias = bias_s[z];
    __nv_bfloat16* oh = ohs[z];
    __nv_bfloat16* ol = ols[z];

    constexpr uint32_t AOFF = 0, ABUF = 32768;           // hi@0 lo@16384, x2 bufs
    constexpr uint32_t BOFF = 65536, BBUF = 32768;       // hi@0 lo@16384, x3 bufs
    // 16 warps: warp tile 32x32
    const int warpM = (wid >> 2) * 32, warpN = (wid & 3) * 32;

    uint32_t a_sw[4], b_sw[4];
    lane_sw(lane, a_sw, b_sw);

    float acc[2][4][4];
    #pragma unroll
    for (int i = 0; i < 2; i++)
        #pragma unroll
        for (int j = 0; j < 4; j++)
            #pragma unroll
            for (int r = 0; r < 4; r++) acc[i][j][r] = 0.f;

    float4 sv[4];
    auto ldgA = [&](int c) {
        const int k0 = c << 6;
        #pragma unroll
        for (int j = 0; j < 4; j++) {
            int g = j * NTHR + tid, row = g >> 4, c4 = g & 15;
            sv[j] = *(const float4*)(Ap + (size_t)(bm + row) * DM + k0 + c4 * 4);
        }
    };
    auto convA = [&](int buf) {
        #pragma unroll
        for (int j = 0; j < 4; j++) {
            int g = j * NTHR + tid, row = g >> 4, c4 = g & 15;
            float vv[4] = {sv[j].x, sv[j].y, sv[j].z, sv[j].w};
            float h[4];
            #pragma unroll
            for (int t = 0; t < 4; t++) h[t] = __bfloat162float(__float2bfloat16(vv[t]));
            uint2 H = { pack_bf2(vv[0], vv[1]), pack_bf2(vv[2], vv[3]) };
            uint2 L = { pack_bf2(vv[0]-h[0], vv[1]-h[1]), pack_bf2(vv[2]-h[2], vv[3]-h[3]) };
            uint32_t d = swz((uint32_t)row * 128 + c4 * 8);
            *(uint2*)(smem + AOFF + buf * ABUF + d)         = H;
            *(uint2*)(smem + AOFF + buf * ABUF + 16384 + d) = L;
        }
    };
    auto issueB = [&](int c, int buf) {
        const int k0 = c << 6;
        #pragma unroll
        for (int i = 0; i < 2; i++) {
            int u = tid + i * NTHR, row = u >> 3, c8 = u & 7;
            uint32_t d = swz((uint32_t)row * 128 + c8 * 16);
            const size_t src = (size_t)(bn + row) * DM + k0 + c8 * 8;
            CP16(sb + BOFF + buf * BBUF + d,         Bh + src);
            CP16(sb + BOFF + buf * BBUF + 16384 + d, Bl + src);
        }
        CP_COMMIT();
    };

    const int C = DM >> 6;  // 16
    ldgA(0);
    issueB(0, 0);
    issueB(1, 1);
    convA(0);
    ldgA(1);
    for (int c = 0; c < C; c++) {
        if (c + 1 < C) CP_WAIT(1); else CP_WAIT(0);
        __syncthreads();
        if (c + 2 < C) issueB(c + 2, (c + 2) % 3);
        compute_chunk<2, 4>(sb + AOFF + (c & 1) * ABUF,
                            sb + AOFF + (c & 1) * ABUF + 16384,
                            sb + BOFF + (c % 3) * BBUF,
                            sb + BOFF + (c % 3) * BBUF + 16384,
                            warpM, warpN, a_sw, b_sw, acc);
        if (c + 1 < C) {
            convA((c + 1) & 1);
            if (c + 2 < C) ldgA(c + 2);
        }
    }

    // epilogue
    const int rr = lane >> 2, cc = (lane & 3) * 2;
    #pragma unroll
    for (int mf = 0; mf < 2; mf++)
        #pragma unroll
        for (int nf = 0; nf < 4; nf++) {
            const int n = bn + warpN + nf * 8 + cc;
            #pragma unroll
            for (int half = 0; half < 2; half++) {
                const int m = bm + warpM + mf * 16 + rr + half * 8;
                const float x = acc[mf][nf][half*2]     + bias[n];
                const float y = acc[mf][nf][half*2 + 1] + bias[n + 1];
                const int b = m >> 11, l = m & 2047;
                if (z < 2) {  // head layout [bh][l][d]
                    const int h = n >> 6, d = n & 63;
                    const size_t o = ((size_t)(b * NH + h) * SEQ + l) * DEP + d;
                    const float hx = __bfloat162float(__float2bfloat16(x));
                    const float hy = __bfloat162float(__float2bfloat16(y));
                    *(uint32_t*)(oh + o) = pack_bf2(x, y);
                    *(uint32_t*)(ol + o) = pack_bf2(x - hx, y - hy);
                } else {      // V transposed [bh][d][l]
                    #pragma unroll
                    for (int j = 0; j < 2; j++) {
                        const int nn = n + j;
                        const int h = nn >> 6, d = nn & 63;
                        const float v = j ? y : x;
                        const __nv_bfloat16 hv = __float2bfloat16(v);
                        const size_t o = ((size_t)(b * NH + h) * DEP + d) * SEQ + l;
                        oh[o] = hv;
                        ol[o] = __float2bfloat16(v - __bfloat162float(hv));
                    }
                }
            }
        }
}

// ---------------------------------------------------------------------------
// Scores: pre-split A,B (K=64), fused scale+mask, write S fp32 + softmax partials
// CTA 128x128, 512 thr.
// ---------------------------------------------------------------------------
__global__ void __launch_bounds__(NTHR, 1)
gemm_scores(const __nv_bfloat16* __restrict__ Ahi, const __nv_bfloat16* __restrict__ Alo,
            const __nv_bfloat16* __restrict__ Bhi, const __nv_bfloat16* __restrict__ Blo,
            const int* __restrict__ mask, float* __restrict__ S,
            float* __restrict__ pmax, float* __restrict__ psum)
{
    extern __shared__ char smem[];
    const uint32_t sb = smem_u32(smem);
    const int tid = threadIdx.x, lane = tid & 31, wid = tid >> 5;
    const int bn = blockIdx.x * 128, bm = blockIdx.y * 128, z = blockIdx.z;

    const __nv_bfloat16* Ah = Ahi + (size_t)z * SEQ * DEP;
    const __nv_bfloat16* Al = Alo + (size_t)z * SEQ * DEP;
    const __nv_bfloat16* Bh = Bhi + (size_t)z * SEQ * DEP;
    const __nv_bfloat16* Bl = Blo + (size_t)z * SEQ * DEP;

    const int warpM = (wid >> 2) * 32, warpN = (wid & 3) * 32;
    uint32_t a_sw[4], b_sw[4];
    lane_sw(lane, a_sw, b_sw);

    // load A(128x64 hi/lo) @0/16384, B @32768/49152
    #pragma unroll
    for (int i = 0; i < 2; i++) {
        int u = tid + i * NTHR, row = u >> 3, c8 = u & 7;
        uint32_t d = swz((uint32_t)row * 128 + c8 * 16);
        const size_t sa = (size_t)(bm + row) * DEP + c8 * 8;
        const size_t sbo = (size_t)(bn + row) * DEP + c8 * 8;
        CP16(sb + d,         Ah + sa);
        CP16(sb + 16384 + d, Al + sa);
        CP16(sb + 32768 + d, Bh + sbo);
        CP16(sb + 49152 + d, Bl + sbo);
    }
    CP_COMMIT();
    CP_WAIT(0);
    __syncthreads();

    float acc[2][4][4];
    #pragma unroll
    for (int i = 0; i < 2; i++)
        #pragma unroll
        for (int j = 0; j < 4; j++)
            #pragma unroll
            for (int r = 0; r < 4; r++) acc[i][j][r] = 0.f;

    compute_chunk<2, 4>(sb, sb + 16384, sb + 32768, sb + 49152,
                        warpM, warpN, a_sw, b_sw, acc);

    // epilogue: scale + mask, write S, accumulate partials
    const int rr = lane >> 2, cc = (lane & 3) * 2;
    #pragma unroll
    for (int mf = 0; mf < 2; mf++)
        #pragma unroll
        for (int half = 0; half < 2; half++) {
            const int m = bm + warpM + mf * 16 + rr + half * 8;
            #pragma unroll
            for (int nf = 0; nf < 4; nf++) {
                const int n = bn + warpN + nf * 8 + cc;
                const int2 mk = *(const int2*)(mask + ((size_t)(z >> 4) * SEQ + m) * SEQ + n);
                float x = acc[mf][nf][half*2]     * 0.125f + (float)mk.x * (-1e9f);
                float y = acc[mf][nf][half*2 + 1] * 0.125f + (float)mk.y * (-1e9f);
                acc[mf][nf][half*2] = x; acc[mf][nf][half*2+1] = y;
                float2 v = {x, y};
                *(float2*)(S + ((size_t)z * SEQ + m) * SEQ + n) = v;
            }
        }

    // per-(row, warp-column) max & expsum
    float* smax = (float*)(smem + 65536);   // [4][128]
    float* ssum = smax + 512;
    #pragma unroll
    for (int mf = 0; mf < 2; mf++)
        #pragma unroll
        for (int half = 0; half < 2; half++) {
            float mx = -3.4e38f;
            #pragma unroll
            for (int nf = 0; nf < 4; nf++) {
                mx = fmaxf(mx, acc[mf][nf][half*2]);
                mx = fmaxf(mx, acc[mf][nf][half*2+1]);
            }
            mx = fmaxf(mx, __shfl_xor_sync(0xffffffffu, mx, 1));
            mx = fmaxf(mx, __shfl_xor_sync(0xffffffffu, mx, 2));
            float sm = 0.f;
            #pragma unroll
            for (int nf = 0; nf < 4; nf++) {
                sm += __expf(acc[mf][nf][half*2]   - mx);
                sm += __expf(acc[mf][nf][half*2+1] - mx);
            }
            sm += __shfl_xor_sync(0xffffffffu, sm, 1);
            sm += __shfl_xor_sync(0xffffffffu, sm, 2);
            if ((lane & 3) == 0) {
                const int r = warpM + mf * 16 + rr + half * 8;
                smax[(wid & 3) * 128 + r] = mx;
                ssum[(wid & 3) * 128 + r] = sm;
            }
        }
    __syncthreads();
    if (tid < 128) {
        float M = smax[tid];
        M = fmaxf(M, smax[128 + tid]);
        M = fmaxf(M, smax[256 + tid]);
        M = fmaxf(M, smax[384 + tid]);
        float Zp = 0.f;
        #pragma unroll
        for (int w = 0; w < 4; w++)
            Zp += ssum[w * 128 + tid] * __expf(smax[w * 128 + tid] - M);
        const size_t o = ((size_t)z * 16 + blockIdx.x) * SEQ + bm + tid;
        pmax[o] = M;
        psum[o] = Zp;
    }
}

// ---------------------------------------------------------------------------
// Combine partials -> row max M and invZ
// ---------------------------------------------------------------------------
__global__ void __launch_bounds__(256)
combine_kernel(const float* __restrict__ pmax, const float* __restrict__ psum,
               float* __restrict__ gM, float* __restrict__ gInvZ)
{
    const int R = blockIdx.x * 256 + threadIdx.x;   // 0..65535
    const int bh = R >> 11, m = R & 2047;
    float mx[16];
    float M = -3.4e38f;
    #pragma unroll
    for (int t = 0; t < 16; t++) {
        mx[t] = pmax[((size_t)bh * 16 + t) * SEQ + m];
        M = fmaxf(M, mx[t]);
    }
    float Z = 0.f;
    #pragma unroll
    for (int t = 0; t < 16; t++)
        Z += psum[((size_t)bh * 16 + t) * SEQ + m] * __expf(mx[t] - M);
    gM[R] = M;
    gInvZ[R] = 1.0f / Z;
}

// ---------------------------------------------------------------------------
// AV: A = raw S fp32 -> softmax finalize (w = exp(s-M)*invZ), write w in place,
// split to hi/lo for 3-term MMA against pre-split V^T. CTA 128x64, 512 thr.
// ---------------------------------------------------------------------------
__global__ void __launch_bounds__(NTHR, 1)
gemm_av(float* __restrict__ S,
        const __nv_bfloat16* __restrict__ Bhi, const __nv_bfloat16* __restrict__ Blo,
        const float* __restrict__ gM, const float* __restrict__ gInvZ,
        __nv_bfloat16* __restrict__ oh, __nv_bfloat16* __restrict__ ol)
{
    extern __shared__ char smem[];
    const uint32_t sb = smem_u32(smem);
    const int tid = threadIdx.x, lane = tid & 31, wid = tid >> 5;
    const int bm = blockIdx.y * 128, z = blockIdx.z;

    float* Sp = S + (size_t)z * SEQ * SEQ;
    const __nv_bfloat16* Bh = Bhi + (size_t)z * DEP * SEQ;
    const __nv_bfloat16* Bl = Blo + (size_t)z * DEP * SEQ;
    const int Rbase = z * SEQ + bm;

    constexpr uint32_t AOFF = 0, ABUF = 32768;      // hi@0 lo@16384, x2
    constexpr uint32_t BOFF = 65536, BBUF = 16384;  // hi@0 lo@8192, x3
    // 16 warps: warp tile 16x32
    const int warpM = (wid >> 1) * 16, warpN = (wid & 1) * 32;

    uint32_t a_sw[4], b_sw[4];
    lane_sw(lane, a_sw, b_sw);

    float acc[1][4][4];
    #pragma unroll
    for (int j = 0; j < 4; j++)
        #pragma unroll
        for (int r = 0; r < 4; r++) acc[0][j][r] = 0.f;

    float4 sv[4];
    auto ldgA = [&](int c) {
        const int k0 = c << 6;
        #pragma unroll
        for (int j = 0; j < 4; j++) {
            int g = j * NTHR + tid, row = g >> 4, c4 = g & 15;
            sv[j] = *(const float4*)(Sp + (size_t)(bm + row) * SEQ + k0 + c4 * 4);
        }
    };
    auto convA = [&](int c, int buf) {
        const int k0 = c << 6;
        #pragma unroll
        for (int j = 0; j < 4; j++) {
            int g = j * NTHR + tid, row = g >> 4, c4 = g & 15;
            const float M = gM[Rbase + row], iZ = gInvZ[Rbase + row];
            float vv[4];
            vv[0] = __expf(sv[j].x - M) * iZ;
            vv[1] = __expf(sv[j].y - M) * iZ;
            vv[2] = __expf(sv[j].z - M) * iZ;
            vv[3] = __expf(sv[j].w - M) * iZ;
            *(float4*)(Sp + (size_t)(bm + row) * SEQ + k0 + c4 * 4) =
                make_float4(vv[0], vv[1], vv[2], vv[3]);
            float h[4];
            #pragma unroll
            for (int t = 0; t < 4; t++) h[t] = __bfloat162float(__float2bfloat16(vv[t]));
            uint2 H = { pack_bf2(vv[0], vv[1]), pack_bf2(vv[2], vv[3]) };
            uint2 L = { pack_bf2(vv[0]-h[0], vv[1]-h[1]), pack_bf2(vv[2]-h[2], vv[3]-h[3]) };
            uint32_t d = swz((uint32_t)row * 128 + c4 * 8);
            *(uint2*)(smem + AOFF + buf * ABUF + d)         = H;
            *(uint2*)(smem + AOFF + buf * ABUF + 16384 + d) = L;
        }
    };
    auto issueB = [&](int c, int buf) {
        const int k0 = c << 6;
        {
            int u = tid, row = u >> 3, c8 = u & 7;
            uint32_t d = swz((uint32_t)row * 128 + c8 * 16);
            const size_t src = (size_t)row * SEQ + k0 + c8 * 8;
            CP16(sb + BOFF + buf * BBUF + d,        Bh + src);
            CP16(sb + BOFF + buf * BBUF + 8192 + d, Bl + src);
        }
        CP_COMMIT();
    };

    const int C = SEQ >> 6;  // 32
    ldgA(0);
    issueB(0, 0);
    issueB(1, 1);
    convA(0, 0);
    ldgA(1);
    for (int c = 0; c < C; c++) {
        if (c + 1 < C) CP_WAIT(1); else CP_WAIT(0);
        __syncthreads();
        if (c + 2 < C) issueB(c + 2, (c + 2) % 3);
        compute_chunk<1, 4>(sb + AOFF + (c & 1) * ABUF,
                            sb + AOFF + (c & 1) * ABUF + 16384,
                            sb + BOFF + (c % 3) * BBUF,
                            sb + BOFF + (c % 3) * BBUF + 8192,
                            warpM, warpN, a_sw, b_sw, acc);
        if (c + 1 < C) {
            convA(c + 1, (c + 1) & 1);
            if (c + 2 < C) ldgA(c + 2);
        }
    }

    // epilogue -> at hi/lo [b*SEQ+m][h*DEP+n]
    const int rr = lane >> 2, cc = (lane & 3) * 2;
    #pragma unroll
    for (int nf = 0; nf < 4; nf++) {
        const int n = warpN + nf * 8 + cc;
        #pragma unroll
        for (int half = 0; half < 2; half++) {
            const int m = bm + warpM + rr + half * 8;
            const float x = acc[0][nf][half*2];
            const float y = acc[0][nf][half*2+1];
            const size_t o = ((size_t)((z >> 4) * SEQ + m)) * DM + (z & 15) * DEP + n;
            const float hx = __bfloat162float(__float2bfloat16(x));
            const float hy = __bfloat162float(__float2bfloat16(y));
            *(uint32_t*)(oh + o) = pack_bf2(x, y);
            *(uint32_t*)(ol + o) = pack_bf2(x - hx, y - hy);
        }
    }
}

// ---------------------------------------------------------------------------
// Output projection: pre-split A (at) and B (Wo), fp32 out + bias.
// CTA 128x128, 512 thr.
// ---------------------------------------------------------------------------
__global__ void __launch_bounds__(NTHR, 1)
gemm_out(const __nv_bfloat16* __restrict__ Ahi, const __nv_bfloat16* __restrict__ Alo,
         const __nv_bfloat16* __restrict__ Bhi, const __nv_bfloat16* __restrict__ Blo,
         const float* __restrict__ bias, float* __restrict__ outf)
{
    extern __shared__ char smem[];
    const uint32_t sb = smem_u32(smem);
    const int tid = threadIdx.x, lane = tid & 31, wid = tid >> 5;
    const int bn = blockIdx.x * 128, bm = blockIdx.y * 128;

    constexpr uint32_t AOFF = 0, ABUF = 32768;      // x3 bufs
    constexpr uint32_t BOFF = 98304, BBUF = 32768;  // x3 bufs
    const int warpM = (wid >> 2) * 32, warpN = (wid & 3) * 32;

    uint32_t a_sw[4], b_sw[4];
    lane_sw(lane, a_sw, b_sw);

    float acc[2][4][4];
    #pragma unroll
    for (int i = 0; i < 2; i++)
        #pragma unroll
        for (int j = 0; j < 4; j++)
            #pragma unroll
            for (int r = 0; r < 4; r++) acc[i][j][r] = 0.f;

    auto issueAB = [&](int c, int buf) {
        const int k0 = c << 6;
        #pragma unroll
        for (int i = 0; i < 2; i++) {
            int u = tid + i * NTHR, row = u >> 3, c8 = u & 7;
            uint32_t d = swz((uint32_t)row * 128 + c8 * 16);
            const size_t sa = (size_t)(bm + row) * DM + k0 + c8 * 8;
            const size_t sbo = (size_t)(bn + row) * DM + k0 + c8 * 8;
            CP16(sb + AOFF + buf * ABUF + d,         Ahi + sa);
            CP16(sb + AOFF + buf * ABUF + 16384 + d, Alo + sa);
            CP16(sb + BOFF + buf * BBUF + d,         Bhi + sbo);
            CP16(sb + BOFF + buf * BBUF + 16384 + d, Blo + sbo);
        }
        CP_COMMIT();
    };

    const int C = DM >> 6;  // 16
    issueAB(0, 0);
    issueAB(1, 1);
    for (int c = 0; c < C; c++) {
        if (c + 1 < C) CP_WAIT(1); else CP_WAIT(0);
        __syncthreads();
        if (c + 2 < C) issueAB(c + 2, (c + 2) % 3);
        compute_chunk<2, 4>(sb + AOFF + (c % 3) * ABUF,
                            sb + AOFF + (c % 3) * ABUF + 16384,
                            sb + BOFF + (c % 3) * BBUF,
                            sb + BOFF + (c % 3) * BBUF + 16384,
                            warpM, warpN, a_sw, b_sw, acc);
    }

    const int rr = lane >> 2, cc = (lane & 3) * 2;
    #pragma unroll
    for (int mf = 0; mf < 2; mf++)
        #pragma unroll
        for (int nf = 0; nf < 4; nf++) {
            const int n = bn + warpN + nf * 8 + cc;
            #pragma unroll
            for (int half = 0; half < 2; half++) {
                const int m = bm + warpM + mf * 16 + rr + half * 8;
                float2 v = { acc[mf][nf][half*2] + bias[n],
                             acc[mf][nf][half*2+1] + bias[n+1] };
                *(float2*)(outf + (size_t)m * DM + n) = v;
            }
        }
}

// ---------------------------------------------------------------------------
extern "C" void kernel_launch(void* const* d_in, const int* in_sizes, int n_in,
                              void* d_out, int out_size)
{
    const float* q    = (const float*)d_in[0];
    const float* k    = (const float*)d_in[1];
    const float* v    = (const float*)d_in[2];
    const int*   mask = (const int*)  d_in[3];
    const float* Wq   = (const float*)d_in[4];
    const float* bq   = (const float*)d_in[5];
    const float* Wk   = (const float*)d_in[6];
    const float* bk   = (const float*)d_in[7];
    const float* Wv   = (const float*)d_in[8];
    const float* bv   = (const float*)d_in[9];
    const float* Wo   = (const float*)d_in[10];
    const float* bo   = (const float*)d_in[11];

    float* out   = (float*)d_out;
    float* attnW = out + (size_t)MTOT * DM;

    __nv_bfloat16 *wqh,*wql,*wkh,*wkl,*wvh,*wvl,*woh,*wol;
    __nv_bfloat16 *qhh,*qhl,*khh,*khl,*vth,*vtl,*ath,*atl;
    float *pmax,*psum,*gM,*gZ;
    cudaGetSymbolAddress((void**)&wqh, g_wq_hi); cudaGetSymbolAddress((void**)&wql, g_wq_lo);
    cudaGetSymbolAddress((void**)&wkh, g_wk_hi); cudaGetSymbolAddress((void**)&wkl, g_wk_lo);
    cudaGetSymbolAddress((void**)&wvh, g_wv_hi); cudaGetSymbolAddress((void**)&wvl, g_wv_lo);
    cudaGetSymbolAddress((void**)&woh, g_wo_hi); cudaGetSymbolAddress((void**)&wol, g_wo_lo);
    cudaGetSymbolAddress((void**)&qhh, g_qh_hi); cudaGetSymbolAddress((void**)&qhl, g_qh_lo);
    cudaGetSymbolAddress((void**)&khh, g_kh_hi); cudaGetSymbolAddress((void**)&khl, g_kh_lo);
    cudaGetSymbolAddress((void**)&vth, g_vt_hi); cudaGetSymbolAddress((void**)&vtl, g_vt_lo);
    cudaGetSymbolAddress((void**)&ath, g_at_hi); cudaGetSymbolAddress((void**)&atl, g_at_lo);
    cudaGetSymbolAddress((void**)&pmax, g_pmax); cudaGetSymbolAddress((void**)&psum, g_psum);
    cudaGetSymbolAddress((void**)&gM, g_M);      cudaGetSymbolAddress((void**)&gZ, g_invZ);

    const int SM_PROJ = 65536 + 3 * 32768;   // 163840
    const int SM_SC   = 65536 + 4096;        // 69632
    const int SM_AV   = 65536 + 3 * 16384;   // 114688
    const int SM_OUT  = 6 * 32768;           // 196608
    cudaFuncSetAttribute(gemm_proj,   cudaFuncAttributeMaxDynamicSharedMemorySize, SM_PROJ);
    cudaFuncSetAttribute(gemm_scores, cudaFuncAttributeMaxDynamicSharedMemorySize, SM_SC);
    cudaFuncSetAttribute(gemm_av,     cudaFuncAttributeMaxDynamicSharedMemorySize, SM_AV);
    cudaFuncSetAttribute(gemm_out,    cudaFuncAttributeMaxDynamicSharedMemorySize, SM_OUT);

    // 1. weight transposes + splits (one launch)
    transpose_split_kernel<<<dim3(32, 32, 4), dim3(32, 8)>>>(
        Wq, Wk, Wv, Wo, wqh, wkh, wvh, woh, wql, wkl, wvl, wol);

    // 2. Q/K/V projections (one launch, z selects)
    gemm_proj<<<dim3(8, 32, 3), NTHR, SM_PROJ>>>(
        q, k, v, wqh, wkh, wvh, wql, wkl, wvl, bq, bk, bv,
        qhh, khh, vth, qhl, khl, vtl);

    // 3. scores + mask + softmax partials (raw S into attnW region)
    gemm_scores<<<dim3(16, 16, BH), NTHR, SM_SC>>>(
        qhh, qhl, khh, khl, mask, attnW, pmax, psum);

    // 4. combine partials -> per-row M, invZ
    combine_kernel<<<BH * SEQ / 256, 256>>>(pmax, psum, gM, gZ);

    // 5. AV with fused softmax finalize (weights written in place)
    gemm_av<<<dim3(1, 16, BH), NTHR, SM_AV>>>(
        attnW, vth, vtl, gM, gZ, ath, atl);

    // 6. output projection
    gemm_out<<<dim3(8, 32, 1), NTHR, SM_OUT>>>(ath, atl, woh, wol, bo, out);
}

// round 7
// speedup vs baseline: 1.5376x; 1.5376x over previous
#include <cuda_runtime.h>
#include <cuda_bf16.h>
#include <cstdint>

#define SEQ   2048
#define DM    1024
#define NH    16
#define DEP   64
#define MTOT  4096
#define BH    32

// ---------------------------------------------------------------------------
// Device scratch (allocation-free)
// ---------------------------------------------------------------------------
__device__ __nv_bfloat16 g_xq_hi[MTOT*DM], g_xq_lo[MTOT*DM];
__device__ __nv_bfloat16 g_xk_hi[MTOT*DM], g_xk_lo[MTOT*DM];
__device__ __nv_bfloat16 g_xv_hi[MTOT*DM], g_xv_lo[MTOT*DM];
__device__ __nv_bfloat16 g_wq_hi[DM*DM], g_wq_lo[DM*DM];
__device__ __nv_bfloat16 g_wk_hi[DM*DM], g_wk_lo[DM*DM];
__device__ __nv_bfloat16 g_wv_hi[DM*DM], g_wv_lo[DM*DM];
__device__ __nv_bfloat16 g_wo_hi[DM*DM], g_wo_lo[DM*DM];
__device__ __nv_bfloat16 g_qh_hi[BH*SEQ*DEP], g_qh_lo[BH*SEQ*DEP];
__device__ __nv_bfloat16 g_kh_hi[BH*SEQ*DEP], g_kh_lo[BH*SEQ*DEP];
__device__ __nv_bfloat16 g_vt_hi[BH*DEP*SEQ], g_vt_lo[BH*DEP*SEQ];
__device__ __nv_bfloat16 g_at_hi[MTOT*DM],    g_at_lo[MTOT*DM];
__device__ float g_pmax[BH*8*SEQ], g_psum[BH*8*SEQ];
__device__ float g_M[BH*SEQ], g_invZ[BH*SEQ];

// ---------------------------------------------------------------------------
// Helpers
// ---------------------------------------------------------------------------
__device__ __forceinline__ uint32_t smem_u32(const void* p) {
    uint32_t a;
    asm("{ .reg .u64 t; cvta.to.shared.u64 t, %1; cvt.u32.u64 %0, t; }"
        : "=r"(a) : "l"(p));
    return a;
}
#define CP16(s, g)  asm volatile("cp.async.cg.shared.global [%0], [%1], 16;" :: "r"(s), "l"(g))
#define CP_COMMIT() asm volatile("cp.async.commit_group;" ::: "memory")
#define CP_WAIT(n)  asm volatile("cp.async.wait_group %0;" :: "n"(n) : "memory")

#define LDSM4(R, addr) \
    asm volatile("ldmatrix.sync.aligned.m8n8.x4.shared.b16 {%0,%1,%2,%3}, [%4];" \
        : "=r"((R)[0]), "=r"((R)[1]), "=r"((R)[2]), "=r"((R)[3]) : "r"(addr))

#define MMA16816(d, a, b) \
    asm volatile("mma.sync.aligned.m16n8k16.row.col.f32.bf16.bf16.f32 " \
        "{%0,%1,%2,%3}, {%4,%5,%6,%7}, {%8,%9}, {%0,%1,%2,%3};" \
        : "+f"((d)[0]), "+f"((d)[1]), "+f"((d)[2]), "+f"((d)[3]) \
        : "r"((a)[0]), "r"((a)[1]), "r"((a)[2]), "r"((a)[3]), "r"((b)[0]), "r"((b)[1]))

__device__ __forceinline__ uint32_t swz(uint32_t b) { return b ^ ((b >> 3) & 0x70); }

__device__ __forceinline__ uint32_t pack_bf2(float x, float y) {
    __nv_bfloat162 t;
    t.x = __float2bfloat16(x);
    t.y = __float2bfloat16(y);
    return *(uint32_t*)&t;
}

__device__ __forceinline__ void lane_sw(int lane, uint32_t* a_sw, uint32_t* b_sw) {
    #pragma unroll
    for (int kk = 0; kk < 4; kk++) {
        a_sw[kk] = swz(((uint32_t)(lane & 15) << 7) + kk * 32 + ((uint32_t)(lane >> 4) << 4));
        b_sw[kk] = swz((((uint32_t)((lane & 7) | ((lane >> 4) << 3))) << 7)
                       + kk * 32 + (((uint32_t)(lane >> 3) & 1) << 4));
    }
}

// 64-wide K chunk, 3-term split-bf16 MMA. B fragments loaded per 16-col pair
// to bound register pressure at larger NF.
template<int MF, int NF>
__device__ __forceinline__ void compute_chunk(
    uint32_t AH, uint32_t AL, uint32_t BHb, uint32_t BLb,
    int warpM, int warpN, const uint32_t* a_sw, const uint32_t* b_sw,
    float (*acc)[NF][4])
{
    #pragma unroll
    for (int kk = 0; kk < 4; kk++) {
        uint32_t ah[MF][4], al[MF][4];
        #pragma unroll
        for (int mf = 0; mf < MF; mf++) {
            const uint32_t ro = (uint32_t)(warpM + mf * 16) * 128;
            LDSM4(ah[mf], AH + ro + a_sw[kk]);
            LDSM4(al[mf], AL + ro + a_sw[kk]);
        }
        #pragma unroll
        for (int p = 0; p < NF / 2; p++) {
            const uint32_t ro = (uint32_t)(warpN + p * 16) * 128;
            uint32_t th[4], tl[4];
            LDSM4(th, BHb + ro + b_sw[kk]);
            LDSM4(tl, BLb + ro + b_sw[kk]);
            #pragma unroll
            for (int mf = 0; mf < MF; mf++) {
                MMA16816(acc[mf][2*p],   ah[mf], (th + 0));
                MMA16816(acc[mf][2*p],   ah[mf], (tl + 0));
                MMA16816(acc[mf][2*p],   al[mf], (th + 0));
                MMA16816(acc[mf][2*p+1], ah[mf], (th + 2));
                MMA16816(acc[mf][2*p+1], ah[mf], (tl + 2));
                MMA16816(acc[mf][2*p+1], al[mf], (th + 2));
            }
        }
    }
}

// ---------------------------------------------------------------------------
// q/k/v fp32 -> bf16 hi/lo (z selects tensor)
// ---------------------------------------------------------------------------
__global__ void split4_kernel(const float* q, const float* k, const float* v,
                              __nv_bfloat16* qh, __nv_bfloat16* kh, __nv_bfloat16* vh,
                              __nv_bfloat16* ql, __nv_bfloat16* kl, __nv_bfloat16* vl)
{
    const float* xs[3] = {q, k, v};
    __nv_bfloat16* hs[3] = {qh, kh, vh};
    __nv_bfloat16* ls[3] = {ql, kl, vl};
    const int z = blockIdx.z;
    const int i = blockIdx.x * blockDim.x + threadIdx.x;
    float4 f = ((const float4*)xs[z])[i];
    float vv[4] = {f.x, f.y, f.z, f.w};
    __nv_bfloat16 hb[4], lb[4];
    #pragma unroll
    for (int j = 0; j < 4; j++) {
        hb[j] = __float2bfloat16(vv[j]);
        lb[j] = __float2bfloat16(vv[j] - __bfloat162float(hb[j]));
    }
    *(uint2*)(hs[z] + (size_t)i * 4) = *(uint2*)hb;
    *(uint2*)(ls[z] + (size_t)i * 4) = *(uint2*)lb;
}

// ---------------------------------------------------------------------------
// W[k][n] fp32 -> Wt[n][k] bf16 hi/lo; 4 matrices via z
// ---------------------------------------------------------------------------
__global__ void transpose_split_kernel(
    const float* W0, const float* W1, const float* W2, const float* W3,
    __nv_bfloat16* h0, __nv_bfloat16* h1, __nv_bfloat16* h2, __nv_bfloat16* h3,
    __nv_bfloat16* l0, __nv_bfloat16* l1, __nv_bfloat16* l2, __nv_bfloat16* l3)
{
    const float* Ws[4] = {W0, W1, W2, W3};
    __nv_bfloat16* hs[4] = {h0, h1, h2, h3};
    __nv_bfloat16* ls[4] = {l0, l1, l2, l3};
    const int z = blockIdx.z;
    const float* W = Ws[z];
    __nv_bfloat16* hi = hs[z];
    __nv_bfloat16* lo = ls[z];

    __shared__ float s[32][33];
    const int bx = blockIdx.x * 32, by = blockIdx.y * 32;
    const int tx = threadIdx.x, ty = threadIdx.y;  // 32 x 8
    #pragma unroll
    for (int j = 0; j < 4; j++)
        s[ty + j * 8][tx] = W[(size_t)(by + ty + j * 8) * DM + bx + tx];
    __syncthreads();
    #pragma unroll
    for (int j = 0; j < 4; j++) {
        int n = bx + ty + j * 8, k = by + tx;
        float v = s[tx][ty + j * 8];
        __nv_bfloat16 h = __float2bfloat16(v);
        hi[(size_t)n * DM + k] = h;
        lo[(size_t)n * DM + k] = __float2bfloat16(v - __bfloat162float(h));
    }
}

// ---------------------------------------------------------------------------
// Projections: pre-split A (x q/k/v) and B (W). CTA 256x128, warp 64x64.
// ---------------------------------------------------------------------------
__global__ void __launch_bounds__(256, 1)
gemm_proj(const __nv_bfloat16* __restrict__ xqh, const __nv_bfloat16* __restrict__ xkh,
          const __nv_bfloat16* __restrict__ xvh,
          const __nv_bfloat16* __restrict__ xql, const __nv_bfloat16* __restrict__ xkl,
          const __nv_bfloat16* __restrict__ xvl,
          const __nv_bfloat16* __restrict__ wqh, const __nv_bfloat16* __restrict__ wkh,
          const __nv_bfloat16* __restrict__ wvh,
          const __nv_bfloat16* __restrict__ wql, const __nv_bfloat16* __restrict__ wkl,
          const __nv_bfloat16* __restrict__ wvl,
          const float* __restrict__ bqp, const float* __restrict__ bkp,
          const float* __restrict__ bvp,
          __nv_bfloat16* __restrict__ qhh, __nv_bfloat16* __restrict__ khh,
          __nv_bfloat16* __restrict__ vth,
          __nv_bfloat16* __restrict__ qhl, __nv_bfloat16* __restrict__ khl,
          __nv_bfloat16* __restrict__ vtl)
{
    extern __shared__ char smem[];
    const uint32_t sb = smem_u32(smem);
    const int tid = threadIdx.x, lane = tid & 31, wid = tid >> 5;
    const int bn = blockIdx.x * 128, bm = blockIdx.y * 256, z = blockIdx.z;

    const __nv_bfloat16* Ahs[3] = {xqh, xkh, xvh};
    const __nv_bfloat16* Als[3] = {xql, xkl, xvl};
    const __nv_bfloat16* Bhs[3] = {wqh, wkh, wvh};
    const __nv_bfloat16* Bls[3] = {wql, wkl, wvl};
    const float* bias_s[3] = {bqp, bkp, bvp};
    __nv_bfloat16* ohs[3] = {qhh, khh, vth};
    __nv_bfloat16* ols[3] = {qhl, khl, vtl};
    const __nv_bfloat16* Ah = Ahs[z];
    const __nv_bfloat16* Al = Als[z];
    const __nv_bfloat16* Bh = Bhs[z];
    const __nv_bfloat16* Bl = Bls[z];
    const float* bias = bias_s[z];
    __nv_bfloat16* oh = ohs[z];
    __nv_bfloat16* ol = ols[z];

    constexpr uint32_t AOFF = 0, ABUF = 65536;        // hi@0 lo@32768, x2
    constexpr uint32_t BOFF = 131072, BBUF = 32768;   // hi@0 lo@16384, x2
    const int warpM = (wid >> 1) * 64, warpN = (wid & 1) * 64;

    uint32_t a_sw[4], b_sw[4];
    lane_sw(lane, a_sw, b_sw);

    float acc[4][8][4];
    #pragma unroll
    for (int i = 0; i < 4; i++)
        #pragma unroll
        for (int j = 0; j < 8; j++)
            #pragma unroll
            for (int r = 0; r < 4; r++) acc[i][j][r] = 0.f;

    auto issueAB = [&](int c, int buf) {
        const int k0 = c << 6;
        #pragma unroll
        for (int i = 0; i < 8; i++) {
            int u = tid + i * 256, row = u >> 3, c8 = u & 7;
            uint32_t d = swz((uint32_t)row * 128 + c8 * 16);
            const size_t src = (size_t)(bm + row) * DM + k0 + c8 * 8;
            CP16(sb + AOFF + buf * ABUF + d,         Ah + src);
            CP16(sb + AOFF + buf * ABUF + 32768 + d, Al + src);
        }
        #pragma unroll
        for (int i = 0; i < 4; i++) {
            int u = tid + i * 256, row = u >> 3, c8 = u & 7;
            uint32_t d = swz((uint32_t)row * 128 + c8 * 16);
            const size_t src = (size_t)(bn + row) * DM + k0 + c8 * 8;
            CP16(sb + BOFF + buf * BBUF + d,         Bh + src);
            CP16(sb + BOFF + buf * BBUF + 16384 + d, Bl + src);
        }
        CP_COMMIT();
    };

    const int C = DM >> 6;  // 16
    issueAB(0, 0);
    for (int c = 0; c < C; c++) {
        CP_WAIT(0);
        __syncthreads();
        if (c + 1 < C) issueAB(c + 1, (c + 1) & 1);
        compute_chunk<4, 8>(sb + AOFF + (c & 1) * ABUF,
                            sb + AOFF + (c & 1) * ABUF + 32768,
                            sb + BOFF + (c & 1) * BBUF,
                            sb + BOFF + (c & 1) * BBUF + 16384,
                            warpM, warpN, a_sw, b_sw, acc);
    }

    // epilogue
    const int rr = lane >> 2, cc = (lane & 3) * 2;
    #pragma unroll
    for (int mf = 0; mf < 4; mf++)
        #pragma unroll
        for (int nf = 0; nf < 8; nf++) {
            const int n = bn + warpN + nf * 8 + cc;
            #pragma unroll
            for (int half = 0; half < 2; half++) {
                const int m = bm + warpM + mf * 16 + rr + half * 8;
                const float x = acc[mf][nf][half*2]     + bias[n];
                const float y = acc[mf][nf][half*2 + 1] + bias[n + 1];
                const int b = m >> 11, l = m & 2047;
                if (z < 2) {  // head layout [bh][l][d]
                    const int h = n >> 6, d = n & 63;
                    const size_t o = ((size_t)(b * NH + h) * SEQ + l) * DEP + d;
                    const float hx = __bfloat162float(__float2bfloat16(x));
                    const float hy = __bfloat162float(__float2bfloat16(y));
                    *(uint32_t*)(oh + o) = pack_bf2(x, y);
                    *(uint32_t*)(ol + o) = pack_bf2(x - hx, y - hy);
                } else {      // V transposed [bh][d][l]
                    #pragma unroll
                    for (int j = 0; j < 2; j++) {
                        const int nn = n + j;
                        const int h = nn >> 6, d = nn & 63;
                        const float v = j ? y : x;
                        const __nv_bfloat16 hv = __float2bfloat16(v);
                        const size_t o = ((size_t)(b * NH + h) * DEP + d) * SEQ + l;
                        oh[o] = hv;
                        ol[o] = __float2bfloat16(v - __bfloat162float(hv));
                    }
                }
            }
        }
}

// ---------------------------------------------------------------------------
// Scores: CTA 128x256, warp 64x64, single-shot K=64. Writes S fp32 + partials.
// ---------------------------------------------------------------------------
__global__ void __launch_bounds__(256, 1)
gemm_scores(const __nv_bfloat16* __restrict__ Ahi, const __nv_bfloat16* __restrict__ Alo,
            const __nv_bfloat16* __restrict__ Bhi, const __nv_bfloat16* __restrict__ Blo,
            const int* __restrict__ mask, float* __restrict__ S,
            float* __restrict__ pmax, float* __restrict__ psum)
{
    extern __shared__ char smem[];
    const uint32_t sb = smem_u32(smem);
    const int tid = threadIdx.x, lane = tid & 31, wid = tid >> 5;
    const int bn = blockIdx.x * 256, bm = blockIdx.y * 128, z = blockIdx.z;

    const __nv_bfloat16* Ah = Ahi + (size_t)z * SEQ * DEP;
    const __nv_bfloat16* Al = Alo + (size_t)z * SEQ * DEP;
    const __nv_bfloat16* Bh = Bhi + (size_t)z * SEQ * DEP;
    const __nv_bfloat16* Bl = Blo + (size_t)z * SEQ * DEP;

    const int warpM = (wid >> 2) * 64, warpN = (wid & 3) * 64;
    uint32_t a_sw[4], b_sw[4];
    lane_sw(lane, a_sw, b_sw);

    // A hi@0 lo@16384; B hi@32768 lo@65536
    #pragma unroll
    for (int i = 0; i < 4; i++) {
        int u = tid + i * 256, row = u >> 3, c8 = u & 7;
        uint32_t d = swz((uint32_t)row * 128 + c8 * 16);
        const size_t sa = (size_t)(bm + row) * DEP + c8 * 8;
        CP16(sb + d,         Ah + sa);
        CP16(sb + 16384 + d, Al + sa);
    }
    #pragma unroll
    for (int i = 0; i < 8; i++) {
        int u = tid + i * 256, row = u >> 3, c8 = u & 7;
        uint32_t d = swz((uint32_t)row * 128 + c8 * 16);
        const size_t sbo = (size_t)(bn + row) * DEP + c8 * 8;
        CP16(sb + 32768 + d, Bh + sbo);
        CP16(sb + 65536 + d, Bl + sbo);
    }
    CP_COMMIT();
    CP_WAIT(0);
    __syncthreads();

    float acc[4][8][4];
    #pragma unroll
    for (int i = 0; i < 4; i++)
        #pragma unroll
        for (int j = 0; j < 8; j++)
            #pragma unroll
            for (int r = 0; r < 4; r++) acc[i][j][r] = 0.f;

    compute_chunk<4, 8>(sb, sb + 16384, sb + 32768, sb + 65536,
                        warpM, warpN, a_sw, b_sw, acc);

    // scale + mask, write S, accumulate partials
    const int rr = lane >> 2, cc = (lane & 3) * 2;
    float* smax = (float*)(smem + 98304);   // [4][128]
    float* ssum = smax + 512;

    #pragma unroll
    for (int mf = 0; mf < 4; mf++)
        #pragma unroll
        for (int half = 0; half < 2; half++) {
            const int r = warpM + mf * 16 + rr + half * 8;
            const int m = bm + r;
            float mx = -3.4e38f;
            #pragma unroll
            for (int nf = 0; nf < 8; nf++) {
                const int n = bn + warpN + nf * 8 + cc;
                const int2 mk = *(const int2*)(mask + ((size_t)(z >> 4) * SEQ + m) * SEQ + n);
                float x = acc[mf][nf][half*2]     * 0.125f + (float)mk.x * (-1e9f);
                float y = acc[mf][nf][half*2 + 1] * 0.125f + (float)mk.y * (-1e9f);
                acc[mf][nf][half*2] = x; acc[mf][nf][half*2+1] = y;
                float2 v = {x, y};
                *(float2*)(S + ((size_t)z * SEQ + m) * SEQ + n) = v;
                mx = fmaxf(mx, fmaxf(x, y));
            }
            mx = fmaxf(mx, __shfl_xor_sync(0xffffffffu, mx, 1));
            mx = fmaxf(mx, __shfl_xor_sync(0xffffffffu, mx, 2));
            float sm = 0.f;
            #pragma unroll
            for (int nf = 0; nf < 8; nf++) {
                sm += __expf(acc[mf][nf][half*2]   - mx);
                sm += __expf(acc[mf][nf][half*2+1] - mx);
            }
            sm += __shfl_xor_sync(0xffffffffu, sm, 1);
            sm += __shfl_xor_sync(0xffffffffu, sm, 2);
            if ((lane & 3) == 0) {
                smax[(wid & 3) * 128 + r] = mx;
                ssum[(wid & 3) * 128 + r] = sm;
            }
        }
    __syncthreads();
    if (tid < 128) {
        float M = smax[tid];
        M = fmaxf(M, smax[128 + tid]);
        M = fmaxf(M, smax[256 + tid]);
        M = fmaxf(M, smax[384 + tid]);
        float Zp = 0.f;
        #pragma unroll
        for (int w = 0; w < 4; w++)
            Zp += ssum[w * 128 + tid] * __expf(smax[w * 128 + tid] - M);
        const size_t o = ((size_t)z * 8 + blockIdx.x) * SEQ + bm + tid;
        pmax[o] = M;
        psum[o] = Zp;
    }
}

// ---------------------------------------------------------------------------
// Combine partials (8 tiles) -> row max M and invZ
// ---------------------------------------------------------------------------
__global__ void __launch_bounds__(256)
combine_kernel(const float* __restrict__ pmax, const float* __restrict__ psum,
               float* __restrict__ gM, float* __restrict__ gInvZ)
{
    const int R = blockIdx.x * 256 + threadIdx.x;   // 0..65535
    const int bh = R >> 11, m = R & 2047;
    float mx[8];
    float M = -3.4e38f;
    #pragma unroll
    for (int t = 0; t < 8; t++) {
        mx[t] = pmax[((size_t)bh * 8 + t) * SEQ + m];
        M = fmaxf(M, mx[t]);
    }
    float Z = 0.f;
    #pragma unroll
    for (int t = 0; t < 8; t++)
        Z += psum[((size_t)bh * 8 + t) * SEQ + m] * __expf(mx[t] - M);
    gM[R] = M;
    gInvZ[R] = 1.0f / Z;
}

// ---------------------------------------------------------------------------
// AV: identical to R4 (889us baseline). CTA 128x64, 8 warps 32x32.
// ---------------------------------------------------------------------------
__global__ void __launch_bounds__(256, 1)
gemm_av(float* __restrict__ S,
        const __nv_bfloat16* __restrict__ Bhi, const __nv_bfloat16* __restrict__ Blo,
        const float* __restrict__ gM, const float* __restrict__ gInvZ,
        __nv_bfloat16* __restrict__ oh, __nv_bfloat16* __restrict__ ol)
{
    extern __shared__ char smem[];
    const uint32_t sb = smem_u32(smem);
    const int tid = threadIdx.x, lane = tid & 31, wid = tid >> 5;
    const int bm = blockIdx.y * 128, z = blockIdx.z;

    float* Sp = S + (size_t)z * SEQ * SEQ;
    const __nv_bfloat16* Bh = Bhi + (size_t)z * DEP * SEQ;
    const __nv_bfloat16* Bl = Blo + (size_t)z * DEP * SEQ;
    const int Rbase = z * SEQ + bm;

    constexpr uint32_t AOFF = 0, ABUF = 32768;      // hi@0 lo@16384, x2
    constexpr uint32_t BOFF = 65536, BBUF = 16384;  // hi@0 lo@8192, x3
    const int warpM = (wid >> 1) * 32, warpN = (wid & 1) * 32;

    uint32_t a_sw[4], b_sw[4];
    lane_sw(lane, a_sw, b_sw);

    float acc[2][4][4];
    #pragma unroll
    for (int i = 0; i < 2; i++)
        #pragma unroll
        for (int j = 0; j < 4; j++)
            #pragma unroll
            for (int r = 0; r < 4; r++) acc[i][j][r] = 0.f;

    float4 sv[8];
    auto ldgA = [&](int c) {
        const int k0 = c << 6;
        #pragma unroll
        for (int j = 0; j < 8; j++) {
            int g = j * 256 + tid, row = g >> 4, c4 = g & 15;
            sv[j] = *(const float4*)(Sp + (size_t)(bm + row) * SEQ + k0 + c4 * 4);
        }
    };
    auto convA = [&](int c, int buf) {
        const int k0 = c << 6;
        #pragma unroll
        for (int j = 0; j < 8; j++) {
            int g = j * 256 + tid, row = g >> 4, c4 = g & 15;
            const float M = gM[Rbase + row], iZ = gInvZ[Rbase + row];
            float vv[4];
            vv[0] = __expf(sv[j].x - M) * iZ;
            vv[1] = __expf(sv[j].y - M) * iZ;
            vv[2] = __expf(sv[j].z - M) * iZ;
            vv[3] = __expf(sv[j].w - M) * iZ;
            *(float4*)(Sp + (size_t)(bm + row) * SEQ + k0 + c4 * 4) =
                make_float4(vv[0], vv[1], vv[2], vv[3]);
            float h[4];
            #pragma unroll
            for (int t = 0; t < 4; t++) h[t] = __bfloat162float(__float2bfloat16(vv[t]));
            uint2 H = { pack_bf2(vv[0], vv[1]), pack_bf2(vv[2], vv[3]) };
            uint2 L = { pack_bf2(vv[0]-h[0], vv[1]-h[1]), pack_bf2(vv[2]-h[2], vv[3]-h[3]) };
            uint32_t d = swz((uint32_t)row * 128 + c4 * 8);
            *(uint2*)(smem + AOFF + buf * ABUF + d)         = H;
            *(uint2*)(smem + AOFF + buf * ABUF + 16384 + d) = L;
        }
    };
    auto issueB = [&](int c, int buf) {
        const int k0 = c << 6;
        #pragma unroll
        for (int i = 0; i < 2; i++) {
            int u = tid + i * 256, row = u >> 3, c8 = u & 7;
            uint32_t d = swz((uint32_t)row * 128 + c8 * 16);
            const size_t src = (size_t)row * SEQ + k0 + c8 * 8;
            CP16(sb + BOFF + buf * BBUF + d,        Bh + src);
            CP16(sb + BOFF + buf * BBUF + 8192 + d, Bl + src);
        }
        CP_COMMIT();
    };

    const int C = SEQ >> 6;  // 32
    ldgA(0);
    issueB(0, 0);
    issueB(1, 1);
    convA(0, 0);
    ldgA(1);
    for (int c = 0; c < C; c++) {
        if (c + 1 < C) CP_WAIT(1); else CP_WAIT(0);
        __syncthreads();
        if (c + 2 < C) issueB(c + 2, (c + 2) % 3);
        compute_chunk<2, 4>(sb + AOFF + (c & 1) * ABUF,
                            sb + AOFF + (c & 1) * ABUF + 16384,
                            sb + BOFF + (c % 3) * BBUF,
                            sb + BOFF + (c % 3) * BBUF + 8192,
                            warpM, warpN, a_sw, b_sw, acc);
        if (c + 1 < C) {
            convA(c + 1, (c + 1) & 1);
            if (c + 2 < C) ldgA(c + 2);
        }
    }

    // epilogue -> at hi/lo [b*SEQ+m][h*DEP+n]
    const int rr = lane >> 2, cc = (lane & 3) * 2;
    #pragma unroll
    for (int mf = 0; mf < 2; mf++)
        #pragma unroll
        for (int nf = 0; nf < 4; nf++) {
            const int n = warpN + nf * 8 + cc;
            #pragma unroll
            for (int half = 0; half < 2; half++) {
                const int m = bm + warpM + mf * 16 + rr + half * 8;
                const float x = acc[mf][nf][half*2];
                const float y = acc[mf][nf][half*2+1];
                const size_t o = ((size_t)((z >> 4) * SEQ + m)) * DM + (z & 15) * DEP + n;
                const float hx = __bfloat162float(__float2bfloat16(x));
                const float hy = __bfloat162float(__float2bfloat16(y));
                *(uint32_t*)(oh + o) = pack_bf2(x, y);
                *(uint32_t*)(ol + o) = pack_bf2(x - hx, y - hy);
            }
        }
}

// ---------------------------------------------------------------------------
// Output projection: CTA 256x128, warp 64x64, pre-split A and B.
// ---------------------------------------------------------------------------
__global__ void __launch_bounds__(256, 1)
gemm_out(const __nv_bfloat16* __restrict__ Ahi, const __nv_bfloat16* __restrict__ Alo,
         const __nv_bfloat16* __restrict__ Bhi, const __nv_bfloat16* __restrict__ Blo,
         const float* __restrict__ bias, float* __restrict__ outf)
{
    extern __shared__ char smem[];
    const uint32_t sb = smem_u32(smem);
    const int tid = threadIdx.x, lane = tid & 31, wid = tid >> 5;
    const int bn = blockIdx.x * 128, bm = blockIdx.y * 256;

    constexpr uint32_t AOFF = 0, ABUF = 65536;        // hi@0 lo@32768, x2
    constexpr uint32_t BOFF = 131072, BBUF = 32768;   // hi@0 lo@16384, x2
    const int warpM = (wid >> 1) * 64, warpN = (wid & 1) * 64;

    uint32_t a_sw[4], b_sw[4];
    lane_sw(lane, a_sw, b_sw);

    float acc[4][8][4];
    #pragma unroll
    for (int i = 0; i < 4; i++)
        #pragma unroll
        for (int j = 0; j < 8; j++)
            #pragma unroll
            for (int r = 0; r < 4; r++) acc[i][j][r] = 0.f;

    auto issueAB = [&](int c, int buf) {
        const int k0 = c << 6;
        #pragma unroll
        for (int i = 0; i < 8; i++) {
            int u = tid + i * 256, row = u >> 3, c8 = u & 7;
            uint32_t d = swz((uint32_t)row * 128 + c8 * 16);
            const size_t src = (size_t)(bm + row) * DM + k0 + c8 * 8;
            CP16(sb + AOFF + buf * ABUF + d,         Ahi + src);
            CP16(sb + AOFF + buf * ABUF + 32768 + d, Alo + src);
        }
        #pragma unroll
        for (int i = 0; i < 4; i++) {
            int u = tid + i * 256, row = u >> 3, c8 = u & 7;
            uint32_t d = swz((uint32_t)row * 128 + c8 * 16);
            const size_t src = (size_t)(bn + row) * DM + k0 + c8 * 8;
            CP16(sb + BOFF + buf * BBUF + d,         Bhi + src);
            CP16(sb + BOFF + buf * BBUF + 16384 + d, Blo + src);
        }
        CP_COMMIT();
    };

    const int C = DM >> 6;  // 16
    issueAB(0, 0);
    for (int c = 0; c < C; c++) {
        CP_WAIT(0);
        __syncthreads();
        if (c + 1 < C) issueAB(c + 1, (c + 1) & 1);
        compute_chunk<4, 8>(sb + AOFF + (c & 1) * ABUF,
                            sb + AOFF + (c & 1) * ABUF + 32768,
                            sb + BOFF + (c & 1) * BBUF,
                            sb + BOFF + (c & 1) * BBUF + 16384,
                            warpM, warpN, a_sw, b_sw, acc);
    }

    const int rr = lane >> 2, cc = (lane & 3) * 2;
    #pragma unroll
    for (int mf = 0; mf < 4; mf++)
        #pragma unroll
        for (int nf = 0; nf < 8; nf++) {
            const int n = bn + warpN + nf * 8 + cc;
            #pragma unroll
            for (int half = 0; half < 2; half++) {
                const int m = bm + warpM + mf * 16 + rr + half * 8;
                float2 v = { acc[mf][nf][half*2] + bias[n],
                             acc[mf][nf][half*2+1] + bias[n+1] };
                *(float2*)(outf + (size_t)m * DM + n) = v;
            }
        }
}

// ---------------------------------------------------------------------------
extern "C" void kernel_launch(void* const* d_in, const int* in_sizes, int n_in,
                              void* d_out, int out_size)
{
    const float* q    = (const float*)d_in[0];
    const float* k    = (const float*)d_in[1];
    const float* v    = (const float*)d_in[2];
    const int*   mask = (const int*)  d_in[3];
    const float* Wq   = (const float*)d_in[4];
    const float* bq   = (const float*)d_in[5];
    const float* Wk   = (const float*)d_in[6];
    const float* bk   = (const float*)d_in[7];
    const float* Wv   = (const float*)d_in[8];
    const float* bv   = (const float*)d_in[9];
    const float* Wo   = (const float*)d_in[10];
    const float* bo   = (const float*)d_in[11];

    float* out   = (float*)d_out;
    float* attnW = out + (size_t)MTOT * DM;

    __nv_bfloat16 *xqh,*xql,*xkh,*xkl,*xvh,*xvl;
    __nv_bfloat16 *wqh,*wql,*wkh,*wkl,*wvh,*wvl,*woh,*wol;
    __nv_bfloat16 *qhh,*qhl,*khh,*khl,*vth,*vtl,*ath,*atl;
    float *pmax,*psum,*gM,*gZ;
    cudaGetSymbolAddress((void**)&xqh, g_xq_hi); cudaGetSymbolAddress((void**)&xql, g_xq_lo);
    cudaGetSymbolAddress((void**)&xkh, g_xk_hi); cudaGetSymbolAddress((void**)&xkl, g_xk_lo);
    cudaGetSymbolAddress((void**)&xvh, g_xv_hi); cudaGetSymbolAddress((void**)&xvl, g_xv_lo);
    cudaGetSymbolAddress((void**)&wqh, g_wq_hi); cudaGetSymbolAddress((void**)&wql, g_wq_lo);
    cudaGetSymbolAddress((void**)&wkh, g_wk_hi); cudaGetSymbolAddress((void**)&wkl, g_wk_lo);
    cudaGetSymbolAddress((void**)&wvh, g_wv_hi); cudaGetSymbolAddress((void**)&wvl, g_wv_lo);
    cudaGetSymbolAddress((void**)&woh, g_wo_hi); cudaGetSymbolAddress((void**)&wol, g_wo_lo);
    cudaGetSymbolAddress((void**)&qhh, g_qh_hi); cudaGetSymbolAddress((void**)&qhl, g_qh_lo);
    cudaGetSymbolAddress((void**)&khh, g_kh_hi); cudaGetSymbolAddress((void**)&khl, g_kh_lo);
    cudaGetSymbolAddress((void**)&vth, g_vt_hi); cudaGetSymbolAddress((void**)&vtl, g_vt_lo);
    cudaGetSymbolAddress((void**)&ath, g_at_hi); cudaGetSymbolAddress((void**)&atl, g_at_lo);
    cudaGetSymbolAddress((void**)&pmax, g_pmax); cudaGetSymbolAddress((void**)&psum, g_psum);
    cudaGetSymbolAddress((void**)&gM, g_M);      cudaGetSymbolAddress((void**)&gZ, g_invZ);

    const int SM_BIG = 2 * 65536 + 2 * 32768;       // 196608
    const int SM_SC  = 98304 + 4096;                // 102400
    const int SM_AV  = 65536 + 3 * 16384;           // 114688
    cudaFuncSetAttribute(gemm_proj,   cudaFuncAttributeMaxDynamicSharedMemorySize, SM_BIG);
    cudaFuncSetAttribute(gemm_scores, cudaFuncAttributeMaxDynamicSharedMemorySize, SM_SC);
    cudaFuncSetAttribute(gemm_av,     cudaFuncAttributeMaxDynamicSharedMemorySize, SM_AV);
    cudaFuncSetAttribute(gemm_out,    cudaFuncAttributeMaxDynamicSharedMemorySize, SM_BIG);

    // 1. input splits + weight transpose/splits
    split4_kernel<<<dim3(MTOT * DM / 4 / 256, 1, 3), 256>>>(
        q, k, v, xqh, xkh, xvh, xql, xkl, xvl);
    transpose_split_kernel<<<dim3(32, 32, 4), dim3(32, 8)>>>(
        Wq, Wk, Wv, Wo, wqh, wkh, wvh, woh, wql, wkl, wvl, wol);

    // 2. Q/K/V projections
    gemm_proj<<<dim3(8, 16, 3), 256, SM_BIG>>>(
        xqh, xkh, xvh, xql, xkl, xvl, wqh, wkh, wvh, wql, wkl, wvl,
        bq, bk, bv, qhh, khh, vth, qhl, khl, vtl);

    // 3. scores + mask + softmax partials
    gemm_scores<<<dim3(8, 16, BH), 256, SM_SC>>>(
        qhh, qhl, khh, khl, mask, attnW, pmax, psum);

    // 4. combine partials
    combine_kernel<<<BH * SEQ / 256, 256>>>(pmax, psum, gM, gZ);

    // 5. AV with fused softmax finalize
    gemm_av<<<dim3(1, 16, BH), 256, SM_AV>>>(
        attnW, vth, vtl, gM, gZ, ath, atl);

    // 6. output projection
    gemm_out<<<dim3(8, 16, 1), 256, SM_BIG>>>(ath, atl, woh, wol, bo, out);
}

// round 8
// speedup vs baseline: 1.5815x; 1.0285x over previous
#include <cuda_runtime.h>
#include <cuda_bf16.h>
#include <cstdint>

#define SEQ   2048
#define DM    1024
#define NH    16
#define DEP   64
#define MTOT  4096
#define BH    32

// ---------------------------------------------------------------------------
// Device scratch (allocation-free)
// ---------------------------------------------------------------------------
__device__ __nv_bfloat16 g_xq_hi[MTOT*DM], g_xq_lo[MTOT*DM];
__device__ __nv_bfloat16 g_xk_hi[MTOT*DM], g_xk_lo[MTOT*DM];
__device__ __nv_bfloat16 g_xv_hi[MTOT*DM], g_xv_lo[MTOT*DM];
__device__ __nv_bfloat16 g_wq_hi[DM*DM], g_wq_lo[DM*DM];
__device__ __nv_bfloat16 g_wk_hi[DM*DM], g_wk_lo[DM*DM];
__device__ __nv_bfloat16 g_wv_hi[DM*DM], g_wv_lo[DM*DM];
__device__ __nv_bfloat16 g_wo_hi[DM*DM], g_wo_lo[DM*DM];
__device__ __nv_bfloat16 g_qh_hi[BH*SEQ*DEP], g_qh_lo[BH*SEQ*DEP];
__device__ __nv_bfloat16 g_kh_hi[BH*SEQ*DEP], g_kh_lo[BH*SEQ*DEP];
__device__ __nv_bfloat16 g_vt_hi[BH*DEP*SEQ], g_vt_lo[BH*DEP*SEQ];
__device__ __nv_bfloat16 g_at_hi[MTOT*DM],    g_at_lo[MTOT*DM];
__device__ float g_pmax[BH*16*SEQ], g_psum[BH*16*SEQ];
__device__ float g_M[BH*SEQ], g_invZ[BH*SEQ];

// ---------------------------------------------------------------------------
// Helpers
// ---------------------------------------------------------------------------
__device__ __forceinline__ uint32_t smem_u32(const void* p) {
    uint32_t a;
    asm("{ .reg .u64 t; cvta.to.shared.u64 t, %1; cvt.u32.u64 %0, t; }"
        : "=r"(a) : "l"(p));
    return a;
}
#define CP16(s, g)  asm volatile("cp.async.cg.shared.global [%0], [%1], 16;" :: "r"(s), "l"(g))
#define CP_COMMIT() asm volatile("cp.async.commit_group;" ::: "memory")
#define CP_WAIT(n)  asm volatile("cp.async.wait_group %0;" :: "n"(n) : "memory")

#define LDSM4(R, addr) \
    asm volatile("ldmatrix.sync.aligned.m8n8.x4.shared.b16 {%0,%1,%2,%3}, [%4];" \
        : "=r"((R)[0]), "=r"((R)[1]), "=r"((R)[2]), "=r"((R)[3]) : "r"(addr))

#define MMA16816(d, a, b) \
    asm volatile("mma.sync.aligned.m16n8k16.row.col.f32.bf16.bf16.f32 " \
        "{%0,%1,%2,%3}, {%4,%5,%6,%7}, {%8,%9}, {%0,%1,%2,%3};" \
        : "+f"((d)[0]), "+f"((d)[1]), "+f"((d)[2]), "+f"((d)[3]) \
        : "r"((a)[0]), "r"((a)[1]), "r"((a)[2]), "r"((a)[3]), "r"((b)[0]), "r"((b)[1]))

__device__ __forceinline__ uint32_t swz(uint32_t b) { return b ^ ((b >> 3) & 0x70); }

__device__ __forceinline__ uint32_t pack_bf2(float x, float y) {
    __nv_bfloat162 t;
    t.x = __float2bfloat16(x);
    t.y = __float2bfloat16(y);
    return *(uint32_t*)&t;
}

__device__ __forceinline__ void lane_sw(int lane, uint32_t* a_sw, uint32_t* b_sw) {
    #pragma unroll
    for (int kk = 0; kk < 4; kk++) {
        a_sw[kk] = swz(((uint32_t)(lane & 15) << 7) + kk * 32 + ((uint32_t)(lane >> 4) << 4));
        b_sw[kk] = swz((((uint32_t)((lane & 7) | ((lane >> 4) << 3))) << 7)
                       + kk * 32 + (((uint32_t)(lane >> 3) & 1) << 4));
    }
}

// 64-wide K chunk, 3-term split-bf16 MMA. B fragments loaded per 16-col pair.
template<int MF, int NF>
__device__ __forceinline__ void compute_chunk(
    uint32_t AH, uint32_t AL, uint32_t BHb, uint32_t BLb,
    int warpM, int warpN, const uint32_t* a_sw, const uint32_t* b_sw,
    float (*acc)[NF][4])
{
    #pragma unroll
    for (int kk = 0; kk < 4; kk++) {
        uint32_t ah[MF][4], al[MF][4];
        #pragma unroll
        for (int mf = 0; mf < MF; mf++) {
            const uint32_t ro = (uint32_t)(warpM + mf * 16) * 128;
            LDSM4(ah[mf], AH + ro + a_sw[kk]);
            LDSM4(al[mf], AL + ro + a_sw[kk]);
        }
        #pragma unroll
        for (int p = 0; p < NF / 2; p++) {
            const uint32_t ro = (uint32_t)(warpN + p * 16) * 128;
            uint32_t th[4], tl[4];
            LDSM4(th, BHb + ro + b_sw[kk]);
            LDSM4(tl, BLb + ro + b_sw[kk]);
            #pragma unroll
            for (int mf = 0; mf < MF; mf++) {
                MMA16816(acc[mf][2*p],   ah[mf], (th + 0));
                MMA16816(acc[mf][2*p],   ah[mf], (tl + 0));
                MMA16816(acc[mf][2*p],   al[mf], (th + 0));
                MMA16816(acc[mf][2*p+1], ah[mf], (th + 2));
                MMA16816(acc[mf][2*p+1], ah[mf], (tl + 2));
                MMA16816(acc[mf][2*p+1], al[mf], (th + 2));
            }
        }
    }
}

// ---------------------------------------------------------------------------
// q/k/v fp32 -> bf16 hi/lo (z selects tensor)
// ---------------------------------------------------------------------------
__global__ void split4_kernel(const float* q, const float* k, const float* v,
                              __nv_bfloat16* qh, __nv_bfloat16* kh, __nv_bfloat16* vh,
                              __nv_bfloat16* ql, __nv_bfloat16* kl, __nv_bfloat16* vl)
{
    const float* xs[3] = {q, k, v};
    __nv_bfloat16* hs[3] = {qh, kh, vh};
    __nv_bfloat16* ls[3] = {ql, kl, vl};
    const int z = blockIdx.z;
    const int i = blockIdx.x * blockDim.x + threadIdx.x;
    float4 f = ((const float4*)xs[z])[i];
    float vv[4] = {f.x, f.y, f.z, f.w};
    __nv_bfloat16 hb[4], lb[4];
    #pragma unroll
    for (int j = 0; j < 4; j++) {
        hb[j] = __float2bfloat16(vv[j]);
        lb[j] = __float2bfloat16(vv[j] - __bfloat162float(hb[j]));
    }
    *(uint2*)(hs[z] + (size_t)i * 4) = *(uint2*)hb;
    *(uint2*)(ls[z] + (size_t)i * 4) = *(uint2*)lb;
}

// ---------------------------------------------------------------------------
// W[k][n] fp32 -> Wt[n][k] bf16 hi/lo; 4 matrices via z
// ---------------------------------------------------------------------------
__global__ void transpose_split_kernel(
    const float* W0, const float* W1, const float* W2, const float* W3,
    __nv_bfloat16* h0, __nv_bfloat16* h1, __nv_bfloat16* h2, __nv_bfloat16* h3,
    __nv_bfloat16* l0, __nv_bfloat16* l1, __nv_bfloat16* l2, __nv_bfloat16* l3)
{
    const float* Ws[4] = {W0, W1, W2, W3};
    __nv_bfloat16* hs[4] = {h0, h1, h2, h3};
    __nv_bfloat16* ls[4] = {l0, l1, l2, l3};
    const int z = blockIdx.z;
    const float* W = Ws[z];
    __nv_bfloat16* hi = hs[z];
    __nv_bfloat16* lo = ls[z];

    __shared__ float s[32][33];
    const int bx = blockIdx.x * 32, by = blockIdx.y * 32;
    const int tx = threadIdx.x, ty = threadIdx.y;  // 32 x 8
    #pragma unroll
    for (int j = 0; j < 4; j++)
        s[ty + j * 8][tx] = W[(size_t)(by + ty + j * 8) * DM + bx + tx];
    __syncthreads();
    #pragma unroll
    for (int j = 0; j < 4; j++) {
        int n = bx + ty + j * 8, k = by + tx;
        float v = s[tx][ty + j * 8];
        __nv_bfloat16 h = __float2bfloat16(v);
        hi[(size_t)n * DM + k] = h;
        lo[(size_t)n * DM + k] = __float2bfloat16(v - __bfloat162float(h));
    }
}

// ---------------------------------------------------------------------------
// Projections: pre-split A (x q/k/v) and B (W). CTA 256x128, warp 64x64.
// ---------------------------------------------------------------------------
__global__ void __launch_bounds__(256, 1)
gemm_proj(const __nv_bfloat16* __restrict__ xqh, const __nv_bfloat16* __restrict__ xkh,
          const __nv_bfloat16* __restrict__ xvh,
          const __nv_bfloat16* __restrict__ xql, const __nv_bfloat16* __restrict__ xkl,
          const __nv_bfloat16* __restrict__ xvl,
          const __nv_bfloat16* __restrict__ wqh, const __nv_bfloat16* __restrict__ wkh,
          const __nv_bfloat16* __restrict__ wvh,
          const __nv_bfloat16* __restrict__ wql, const __nv_bfloat16* __restrict__ wkl,
          const __nv_bfloat16* __restrict__ wvl,
          const float* __restrict__ bqp, const float* __restrict__ bkp,
          const float* __restrict__ bvp,
          __nv_bfloat16* __restrict__ qhh, __nv_bfloat16* __restrict__ khh,
          __nv_bfloat16* __restrict__ vth,
          __nv_bfloat16* __restrict__ qhl, __nv_bfloat16* __restrict__ khl,
          __nv_bfloat16* __restrict__ vtl)
{
    extern __shared__ char smem[];
    const uint32_t sb = smem_u32(smem);
    const int tid = threadIdx.x, lane = tid & 31, wid = tid >> 5;
    const int bn = blockIdx.x * 128, bm = blockIdx.y * 256, z = blockIdx.z;

    const __nv_bfloat16* Ahs[3] = {xqh, xkh, xvh};
    const __nv_bfloat16* Als[3] = {xql, xkl, xvl};
    const __nv_bfloat16* Bhs[3] = {wqh, wkh, wvh};
    const __nv_bfloat16* Bls[3] = {wql, wkl, wvl};
    const float* bias_s[3] = {bqp, bkp, bvp};
    __nv_bfloat16* ohs[3] = {qhh, khh, vth};
    __nv_bfloat16* ols[3] = {qhl, khl, vtl};
    const __nv_bfloat16* Ah = Ahs[z];
    const __nv_bfloat16* Al = Als[z];
    const __nv_bfloat16* Bh = Bhs[z];
    const __nv_bfloat16* Bl = Bls[z];
    const float* bias = bias_s[z];
    __nv_bfloat16* oh = ohs[z];
    __nv_bfloat16* ol = ols[z];

    constexpr uint32_t AOFF = 0, ABUF = 65536;        // hi@0 lo@32768, x2
    constexpr uint32_t BOFF = 131072, BBUF = 32768;   // hi@0 lo@16384, x2
    const int warpM = (wid >> 1) * 64, warpN = (wid & 1) * 64;

    uint32_t a_sw[4], b_sw[4];
    lane_sw(lane, a_sw, b_sw);

    float acc[4][8][4];
    #pragma unroll
    for (int i = 0; i < 4; i++)
        #pragma unroll
        for (int j = 0; j < 8; j++)
            #pragma unroll
            for (int r = 0; r < 4; r++) acc[i][j][r] = 0.f;

    auto issueAB = [&](int c, int buf) {
        const int k0 = c << 6;
        #pragma unroll
        for (int i = 0; i < 8; i++) {
            int u = tid + i * 256, row = u >> 3, c8 = u & 7;
            uint32_t d = swz((uint32_t)row * 128 + c8 * 16);
            const size_t src = (size_t)(bm + row) * DM + k0 + c8 * 8;
            CP16(sb + AOFF + buf * ABUF + d,         Ah + src);
            CP16(sb + AOFF + buf * ABUF + 32768 + d, Al + src);
        }
        #pragma unroll
        for (int i = 0; i < 4; i++) {
            int u = tid + i * 256, row = u >> 3, c8 = u & 7;
            uint32_t d = swz((uint32_t)row * 128 + c8 * 16);
            const size_t src = (size_t)(bn + row) * DM + k0 + c8 * 8;
            CP16(sb + BOFF + buf * BBUF + d,         Bh + src);
            CP16(sb + BOFF + buf * BBUF + 16384 + d, Bl + src);
        }
        CP_COMMIT();
    };

    const int C = DM >> 6;  // 16
    issueAB(0, 0);
    for (int c = 0; c < C; c++) {
        CP_WAIT(0);
        __syncthreads();
        if (c + 1 < C) issueAB(c + 1, (c + 1) & 1);
        compute_chunk<4, 8>(sb + AOFF + (c & 1) * ABUF,
                            sb + AOFF + (c & 1) * ABUF + 32768,
                            sb + BOFF + (c & 1) * BBUF,
                            sb + BOFF + (c & 1) * BBUF + 16384,
                            warpM, warpN, a_sw, b_sw, acc);
    }

    // epilogue
    const int rr = lane >> 2, cc = (lane & 3) * 2;
    #pragma unroll
    for (int mf = 0; mf < 4; mf++)
        #pragma unroll
        for (int nf = 0; nf < 8; nf++) {
            const int n = bn + warpN + nf * 8 + cc;
            #pragma unroll
            for (int half = 0; half < 2; half++) {
                const int m = bm + warpM + mf * 16 + rr + half * 8;
                const float x = acc[mf][nf][half*2]     + bias[n];
                const float y = acc[mf][nf][half*2 + 1] + bias[n + 1];
                const int b = m >> 11, l = m & 2047;
                if (z < 2) {  // head layout [bh][l][d]
                    const int h = n >> 6, d = n & 63;
                    const size_t o = ((size_t)(b * NH + h) * SEQ + l) * DEP + d;
                    const float hx = __bfloat162float(__float2bfloat16(x));
                    const float hy = __bfloat162float(__float2bfloat16(y));
                    *(uint32_t*)(oh + o) = pack_bf2(x, y);
                    *(uint32_t*)(ol + o) = pack_bf2(x - hx, y - hy);
                } else {      // V transposed [bh][d][l]
                    #pragma unroll
                    for (int j = 0; j < 2; j++) {
                        const int nn = n + j;
                        const int h = nn >> 6, d = nn & 63;
                        const float v = j ? y : x;
                        const __nv_bfloat16 hv = __float2bfloat16(v);
                        const size_t o = ((size_t)(b * NH + h) * DEP + d) * SEQ + l;
                        oh[o] = hv;
                        ol[o] = __float2bfloat16(v - __bfloat162float(hv));
                    }
                }
            }
        }
}

// ---------------------------------------------------------------------------
// Scores: CTA 128x128, 128 threads (4 warps of 64x64) -> 2 CTAs/SM.
// Single-shot K=64. Writes raw masked S fp32 + per-128-tile partials.
// ---------------------------------------------------------------------------
__global__ void __launch_bounds__(128, 2)
gemm_scores(const __nv_bfloat16* __restrict__ Ahi, const __nv_bfloat16* __restrict__ Alo,
            const __nv_bfloat16* __restrict__ Bhi, const __nv_bfloat16* __restrict__ Blo,
            const int* __restrict__ mask, float* __restrict__ S,
            float* __restrict__ pmax, float* __restrict__ psum)
{
    extern __shared__ char smem[];
    const uint32_t sb = smem_u32(smem);
    const int tid = threadIdx.x, lane = tid & 31, wid = tid >> 5;
    const int bn = blockIdx.x * 128, bm = blockIdx.y * 128, z = blockIdx.z;

    const __nv_bfloat16* Ah = Ahi + (size_t)z * SEQ * DEP;
    const __nv_bfloat16* Al = Alo + (size_t)z * SEQ * DEP;
    const __nv_bfloat16* Bh = Bhi + (size_t)z * SEQ * DEP;
    const __nv_bfloat16* Bl = Blo + (size_t)z * SEQ * DEP;

    const int warpM = (wid >> 1) * 64, warpN = (wid & 1) * 64;
    uint32_t a_sw[4], b_sw[4];
    lane_sw(lane, a_sw, b_sw);

    // A hi@0 lo@16384; B hi@32768 lo@49152
    #pragma unroll
    for (int i = 0; i < 8; i++) {
        int u = tid + i * 128, row = u >> 3, c8 = u & 7;
        uint32_t d = swz((uint32_t)row * 128 + c8 * 16);
        const size_t sa = (size_t)(bm + row) * DEP + c8 * 8;
        const size_t sbo = (size_t)(bn + row) * DEP + c8 * 8;
        CP16(sb + d,         Ah + sa);
        CP16(sb + 16384 + d, Al + sa);
        CP16(sb + 32768 + d, Bh + sbo);
        CP16(sb + 49152 + d, Bl + sbo);
    }
    CP_COMMIT();
    CP_WAIT(0);
    __syncthreads();

    float acc[4][8][4];
    #pragma unroll
    for (int i = 0; i < 4; i++)
        #pragma unroll
        for (int j = 0; j < 8; j++)
            #pragma unroll
            for (int r = 0; r < 4; r++) acc[i][j][r] = 0.f;

    compute_chunk<4, 8>(sb, sb + 16384, sb + 32768, sb + 49152,
                        warpM, warpN, a_sw, b_sw, acc);

    // scale + mask, write S, accumulate partials
    const int rr = lane >> 2, cc = (lane & 3) * 2;
    float* smax = (float*)(smem + 65536);   // [2][128]
    float* ssum = smax + 256;               // [2][128]

    #pragma unroll
    for (int mf = 0; mf < 4; mf++)
        #pragma unroll
        for (int half = 0; half < 2; half++) {
            const int r = warpM + mf * 16 + rr + half * 8;
            const int m = bm + r;
            float mx = -3.4e38f;
            #pragma unroll
            for (int nf = 0; nf < 8; nf++) {
                const int n = bn + warpN + nf * 8 + cc;
                const int2 mk = *(const int2*)(mask + ((size_t)(z >> 4) * SEQ + m) * SEQ + n);
                float x = acc[mf][nf][half*2]     * 0.125f + (float)mk.x * (-1e9f);
                float y = acc[mf][nf][half*2 + 1] * 0.125f + (float)mk.y * (-1e9f);
                acc[mf][nf][half*2] = x; acc[mf][nf][half*2+1] = y;
                float2 v = {x, y};
                *(float2*)(S + ((size_t)z * SEQ + m) * SEQ + n) = v;
                mx = fmaxf(mx, fmaxf(x, y));
            }
            mx = fmaxf(mx, __shfl_xor_sync(0xffffffffu, mx, 1));
            mx = fmaxf(mx, __shfl_xor_sync(0xffffffffu, mx, 2));
            float sm = 0.f;
            #pragma unroll
            for (int nf = 0; nf < 8; nf++) {
                sm += __expf(acc[mf][nf][half*2]   - mx);
                sm += __expf(acc[mf][nf][half*2+1] - mx);
            }
            sm += __shfl_xor_sync(0xffffffffu, sm, 1);
            sm += __shfl_xor_sync(0xffffffffu, sm, 2);
            if ((lane & 3) == 0) {
                smax[(wid & 1) * 128 + r] = mx;
                ssum[(wid & 1) * 128 + r] = sm;
            }
        }
    __syncthreads();
    {
        float m0 = smax[tid], m1 = smax[128 + tid];
        float M = fmaxf(m0, m1);
        float Zp = ssum[tid] * __expf(m0 - M) + ssum[128 + tid] * __expf(m1 - M);
        const size_t o = ((size_t)z * 16 + blockIdx.x) * SEQ + bm + tid;
        pmax[o] = M;
        psum[o] = Zp;
    }
}

// ---------------------------------------------------------------------------
// Combine partials (16 tiles) -> row max M and invZ
// ---------------------------------------------------------------------------
__global__ void __launch_bounds__(256)
combine_kernel(const float* __restrict__ pmax, const float* __restrict__ psum,
               float* __restrict__ gM, float* __restrict__ gInvZ)
{
    const int R = blockIdx.x * 256 + threadIdx.x;   // 0..65535
    const int bh = R >> 11, m = R & 2047;
    float mx[16];
    float M = -3.4e38f;
    #pragma unroll
    for (int t = 0; t < 16; t++) {
        mx[t] = pmax[((size_t)bh * 16 + t) * SEQ + m];
        M = fmaxf(M, mx[t]);
    }
    float Z = 0.f;
    #pragma unroll
    for (int t = 0; t < 16; t++)
        Z += psum[((size_t)bh * 16 + t) * SEQ + m] * __expf(mx[t] - M);
    gM[R] = M;
    gInvZ[R] = 1.0f / Z;
}

// ---------------------------------------------------------------------------
// AV: A = raw S fp32 -> softmax finalize (w = exp(s-M)*invZ), write w in place,
// split to hi/lo for 3-term MMA against pre-split V^T. CTA 128x64, 8 warps 32x32.
// ---------------------------------------------------------------------------
__global__ void __launch_bounds__(256, 1)
gemm_av(float* __restrict__ S,
        const __nv_bfloat16* __restrict__ Bhi, const __nv_bfloat16* __restrict__ Blo,
        const float* __restrict__ gM, const float* __restrict__ gInvZ,
        __nv_bfloat16* __restrict__ oh, __nv_bfloat16* __restrict__ ol)
{
    extern __shared__ char smem[];
    const uint32_t sb = smem_u32(smem);
    const int tid = threadIdx.x, lane = tid & 31, wid = tid >> 5;
    const int bm = blockIdx.y * 128, z = blockIdx.z;

    float* Sp = S + (size_t)z * SEQ * SEQ;
    const __nv_bfloat16* Bh = Bhi + (size_t)z * DEP * SEQ;
    const __nv_bfloat16* Bl = Blo + (size_t)z * DEP * SEQ;
    const int Rbase = z * SEQ + bm;

    constexpr uint32_t AOFF = 0, ABUF = 32768;      // hi@0 lo@16384, x2
    constexpr uint32_t BOFF = 65536, BBUF = 16384;  // hi@0 lo@8192, x3
    const int warpM = (wid >> 1) * 32, warpN = (wid & 1) * 32;

    uint32_t a_sw[4], b_sw[4];
    lane_sw(lane, a_sw, b_sw);

    float acc[2][4][4];
    #pragma unroll
    for (int i = 0; i < 2; i++)
        #pragma unroll
        for (int j = 0; j < 4; j++)
            #pragma unroll
            for (int r = 0; r < 4; r++) acc[i][j][r] = 0.f;

    float4 sv[8];
    auto ldgA = [&](int c) {
        const int k0 = c << 6;
        #pragma unroll
        for (int j = 0; j < 8; j++) {
            int g = j * 256 + tid, row = g >> 4, c4 = g & 15;
            sv[j] = *(const float4*)(Sp + (size_t)(bm + row) * SEQ + k0 + c4 * 4);
        }
    };
    auto convA = [&](int c, int buf) {
        const int k0 = c << 6;
        #pragma unroll
        for (int j = 0; j < 8; j++) {
            int g = j * 256 + tid, row = g >> 4, c4 = g & 15;
            const float M = gM[Rbase + row], iZ = gInvZ[Rbase + row];
            float vv[4];
            vv[0] = __expf(sv[j].x - M) * iZ;
            vv[1] = __expf(sv[j].y - M) * iZ;
            vv[2] = __expf(sv[j].z - M) * iZ;
            vv[3] = __expf(sv[j].w - M) * iZ;
            *(float4*)(Sp + (size_t)(bm + row) * SEQ + k0 + c4 * 4) =
                make_float4(vv[0], vv[1], vv[2], vv[3]);
            float h[4];
            #pragma unroll
            for (int t = 0; t < 4; t++) h[t] = __bfloat162float(__float2bfloat16(vv[t]));
            uint2 H = { pack_bf2(vv[0], vv[1]), pack_bf2(vv[2], vv[3]) };
            uint2 L = { pack_bf2(vv[0]-h[0], vv[1]-h[1]), pack_bf2(vv[2]-h[2], vv[3]-h[3]) };
            uint32_t d = swz((uint32_t)row * 128 + c4 * 8);
            *(uint2*)(smem + AOFF + buf * ABUF + d)         = H;
            *(uint2*)(smem + AOFF + buf * ABUF + 16384 + d) = L;
        }
    };
    auto issueB = [&](int c, int buf) {
        const int k0 = c << 6;
        #pragma unroll
        for (int i = 0; i < 2; i++) {
            int u = tid + i * 256, row = u >> 3, c8 = u & 7;
            uint32_t d = swz((uint32_t)row * 128 + c8 * 16);
            const size_t src = (size_t)row * SEQ + k0 + c8 * 8;
            CP16(sb + BOFF + buf * BBUF + d,        Bh + src);
            CP16(sb + BOFF + buf * BBUF + 8192 + d, Bl + src);
        }
        CP_COMMIT();
    };

    const int C = SEQ >> 6;  // 32
    ldgA(0);
    issueB(0, 0);
    issueB(1, 1);
    convA(0, 0);
    ldgA(1);
    for (int c = 0; c < C; c++) {
        if (c + 1 < C) CP_WAIT(1); else CP_WAIT(0);
        __syncthreads();
        if (c + 2 < C) issueB(c + 2, (c + 2) % 3);
        compute_chunk<2, 4>(sb + AOFF + (c & 1) * ABUF,
                            sb + AOFF + (c & 1) * ABUF + 16384,
                            sb + BOFF + (c % 3) * BBUF,
                            sb + BOFF + (c % 3) * BBUF + 8192,
                            warpM, warpN, a_sw, b_sw, acc);
        if (c + 1 < C) {
            convA(c + 1, (c + 1) & 1);
            if (c + 2 < C) ldgA(c + 2);
        }
    }

    // epilogue -> at hi/lo [b*SEQ+m][h*DEP+n]
    const int rr = lane >> 2, cc = (lane & 3) * 2;
    #pragma unroll
    for (int mf = 0; mf < 2; mf++)
        #pragma unroll
        for (int nf = 0; nf < 4; nf++) {
            const int n = warpN + nf * 8 + cc;
            #pragma unroll
            for (int half = 0; half < 2; half++) {
                const int m = bm + warpM + mf * 16 + rr + half * 8;
                const float x = acc[mf][nf][half*2];
                const float y = acc[mf][nf][half*2+1];
                const size_t o = ((size_t)((z >> 4) * SEQ + m)) * DM + (z & 15) * DEP + n;
                const float hx = __bfloat162float(__float2bfloat16(x));
                const float hy = __bfloat162float(__float2bfloat16(y));
                *(uint32_t*)(oh + o) = pack_bf2(x, y);
                *(uint32_t*)(ol + o) = pack_bf2(x - hx, y - hy);
            }
        }
}

// ---------------------------------------------------------------------------
// Output projection: CTA 256x128, warp 64x64, pre-split A and B.
// ---------------------------------------------------------------------------
__global__ void __launch_bounds__(256, 1)
gemm_out(const __nv_bfloat16* __restrict__ Ahi, const __nv_bfloat16* __restrict__ Alo,
         const __nv_bfloat16* __restrict__ Bhi, const __nv_bfloat16* __restrict__ Blo,
         const float* __restrict__ bias, float* __restrict__ outf)
{
    extern __shared__ char smem[];
    const uint32_t sb = smem_u32(smem);
    const int tid = threadIdx.x, lane = tid & 31, wid = tid >> 5;
    const int bn = blockIdx.x * 128, bm = blockIdx.y * 256;

    constexpr uint32_t AOFF = 0, ABUF = 65536;        // hi@0 lo@32768, x2
    constexpr uint32_t BOFF = 131072, BBUF = 32768;   // hi@0 lo@16384, x2
    const int warpM = (wid >> 1) * 64, warpN = (wid & 1) * 64;

    uint32_t a_sw[4], b_sw[4];
    lane_sw(lane, a_sw, b_sw);

    float acc[4][8][4];
    #pragma unroll
    for (int i = 0; i < 4; i++)
        #pragma unroll
        for (int j = 0; j < 8; j++)
            #pragma unroll
            for (int r = 0; r < 4; r++) acc[i][j][r] = 0.f;

    auto issueAB = [&](int c, int buf) {
        const int k0 = c << 6;
        #pragma unroll
        for (int i = 0; i < 8; i++) {
            int u = tid + i * 256, row = u >> 3, c8 = u & 7;
            uint32_t d = swz((uint32_t)row * 128 + c8 * 16);
            const size_t src = (size_t)(bm + row) * DM + k0 + c8 * 8;
            CP16(sb + AOFF + buf * ABUF + d,         Ahi + src);
            CP16(sb + AOFF + buf * ABUF + 32768 + d, Alo + src);
        }
        #pragma unroll
        for (int i = 0; i < 4; i++) {
            int u = tid + i * 256, row = u >> 3, c8 = u & 7;
            uint32_t d = swz((uint32_t)row * 128 + c8 * 16);
            const size_t src = (size_t)(bn + row) * DM + k0 + c8 * 8;
            CP16(sb + BOFF + buf * BBUF + d,         Bhi + src);
            CP16(sb + BOFF + buf * BBUF + 16384 + d, Blo + src);
        }
        CP_COMMIT();
    };

    const int C = DM >> 6;  // 16
    issueAB(0, 0);
    for (int c = 0; c < C; c++) {
        CP_WAIT(0);
        __syncthreads();
        if (c + 1 < C) issueAB(c + 1, (c + 1) & 1);
        compute_chunk<4, 8>(sb + AOFF + (c & 1) * ABUF,
                            sb + AOFF + (c & 1) * ABUF + 32768,
                            sb + BOFF + (c & 1) * BBUF,
                            sb + BOFF + (c & 1) * BBUF + 16384,
                            warpM, warpN, a_sw, b_sw, acc);
    }

    const int rr = lane >> 2, cc = (lane & 3) * 2;
    #pragma unroll
    for (int mf = 0; mf < 4; mf++)
        #pragma unroll
        for (int nf = 0; nf < 8; nf++) {
            const int n = bn + warpN + nf * 8 + cc;
            #pragma unroll
            for (int half = 0; half < 2; half++) {
                const int m = bm + warpM + mf * 16 + rr + half * 8;
                float2 v = { acc[mf][nf][half*2] + bias[n],
                             acc[mf][nf][half*2+1] + bias[n+1] };
                *(float2*)(outf + (size_t)m * DM + n) = v;
            }
        }
}

// ---------------------------------------------------------------------------
extern "C" void kernel_launch(void* const* d_in, const int* in_sizes, int n_in,
                              void* d_out, int out_size)
{
    const float* q    = (const float*)d_in[0];
    const float* k    = (const float*)d_in[1];
    const float* v    = (const float*)d_in[2];
    const int*   mask = (const int*)  d_in[3];
    const float* Wq   = (const float*)d_in[4];
    const float* bq   = (const float*)d_in[5];
    const float* Wk   = (const float*)d_in[6];
    const float* bk   = (const float*)d_in[7];
    const float* Wv   = (const float*)d_in[8];
    const float* bv   = (const float*)d_in[9];
    const float* Wo   = (const float*)d_in[10];
    const float* bo   = (const float*)d_in[11];

    float* out   = (float*)d_out;
    float* attnW = out + (size_t)MTOT * DM;

    __nv_bfloat16 *xqh,*xql,*xkh,*xkl,*xvh,*xvl;
    __nv_bfloat16 *wqh,*wql,*wkh,*wkl,*wvh,*wvl,*woh,*wol;
    __nv_bfloat16 *qhh,*qhl,*khh,*khl,*vth,*vtl,*ath,*atl;
    float *pmax,*psum,*gM,*gZ;
    cudaGetSymbolAddress((void**)&xqh, g_xq_hi); cudaGetSymbolAddress((void**)&xql, g_xq_lo);
    cudaGetSymbolAddress((void**)&xkh, g_xk_hi); cudaGetSymbolAddress((void**)&xkl, g_xk_lo);
    cudaGetSymbolAddress((void**)&xvh, g_xv_hi); cudaGetSymbolAddress((void**)&xvl, g_xv_lo);
    cudaGetSymbolAddress((void**)&wqh, g_wq_hi); cudaGetSymbolAddress((void**)&wql, g_wq_lo);
    cudaGetSymbolAddress((void**)&wkh, g_wk_hi); cudaGetSymbolAddress((void**)&wkl, g_wk_lo);
    cudaGetSymbolAddress((void**)&wvh, g_wv_hi); cudaGetSymbolAddress((void**)&wvl, g_wv_lo);
    cudaGetSymbolAddress((void**)&woh, g_wo_hi); cudaGetSymbolAddress((void**)&wol, g_wo_lo);
    cudaGetSymbolAddress((void**)&qhh, g_qh_hi); cudaGetSymbolAddress((void**)&qhl, g_qh_lo);
    cudaGetSymbolAddress((void**)&khh, g_kh_hi); cudaGetSymbolAddress((void**)&khl, g_kh_lo);
    cudaGetSymbolAddress((void**)&vth, g_vt_hi); cudaGetSymbolAddress((void**)&vtl, g_vt_lo);
    cudaGetSymbolAddress((void**)&ath, g_at_hi); cudaGetSymbolAddress((void**)&atl, g_at_lo);
    cudaGetSymbolAddress((void**)&pmax, g_pmax); cudaGetSymbolAddress((void**)&psum, g_psum);
    cudaGetSymbolAddress((void**)&gM, g_M);      cudaGetSymbolAddress((void**)&gZ, g_invZ);

    const int SM_BIG = 2 * 65536 + 2 * 32768;       // 196608
    const int SM_SC  = 65536 + 2048;                // 67584
    const int SM_AV  = 65536 + 3 * 16384;           // 114688
    cudaFuncSetAttribute(gemm_proj,   cudaFuncAttributeMaxDynamicSharedMemorySize, SM_BIG);
    cudaFuncSetAttribute(gemm_scores, cudaFuncAttributeMaxDynamicSharedMemorySize, SM_SC);
    cudaFuncSetAttribute(gemm_av,     cudaFuncAttributeMaxDynamicSharedMemorySize, SM_AV);
    cudaFuncSetAttribute(gemm_out,    cudaFuncAttributeMaxDynamicSharedMemorySize, SM_BIG);

    // 1. input splits + weight transpose/splits
    split4_kernel<<<dim3(MTOT * DM / 4 / 256, 1, 3), 256>>>(
        q, k, v, xqh, xkh, xvh, xql, xkl, xvl);
    transpose_split_kernel<<<dim3(32, 32, 4), dim3(32, 8)>>>(
        Wq, Wk, Wv, Wo, wqh, wkh, wvh, woh, wql, wkl, wvl, wol);

    // 2. Q/K/V projections
    gemm_proj<<<dim3(8, 16, 3), 256, SM_BIG>>>(
        xqh, xkh, xvh, xql, xkl, xvl, wqh, wkh, wvh, wql, wkl, wvl,
        bq, bk, bv, qhh, khh, vth, qhl, khl, vtl);

    // 3. scores + mask + softmax partials (128-thread CTAs, 2/SM)
    gemm_scores<<<dim3(16, 16, BH), 128, SM_SC>>>(
        qhh, qhl, khh, khl, mask, attnW, pmax, psum);

    // 4. combine partials
    combine_kernel<<<BH * SEQ / 256, 256>>>(pmax, psum, gM, gZ);

    // 5. AV with fused softmax finalize
    gemm_av<<<dim3(1, 16, BH), 256, SM_AV>>>(
        attnW, vth, vtl, gM, gZ, ath, atl);

    // 6. output projection
    gemm_out<<<dim3(8, 16, 1), 256, SM_BIG>>>(ath, atl, woh, wol, bo, out);
}

// round 9
// speedup vs baseline: 1.6194x; 1.0240x over previous
#include <cuda_runtime.h>
#include <cuda_bf16.h>
#include <cstdint>

#define SEQ   2048
#define DM    1024
#define NH    16
#define DEP   64
#define MTOT  4096
#define BH    32

// ---------------------------------------------------------------------------
// Device scratch (allocation-free)
// ---------------------------------------------------------------------------
__device__ __nv_bfloat16 g_xq_hi[MTOT*DM], g_xq_lo[MTOT*DM];
__device__ __nv_bfloat16 g_xk_hi[MTOT*DM], g_xk_lo[MTOT*DM];
__device__ __nv_bfloat16 g_xv_hi[MTOT*DM], g_xv_lo[MTOT*DM];
__device__ __nv_bfloat16 g_wq_hi[DM*DM], g_wq_lo[DM*DM];
__device__ __nv_bfloat16 g_wk_hi[DM*DM], g_wk_lo[DM*DM];
__device__ __nv_bfloat16 g_wv_hi[DM*DM], g_wv_lo[DM*DM];
__device__ __nv_bfloat16 g_wo_hi[DM*DM], g_wo_lo[DM*DM];
__device__ __nv_bfloat16 g_qh_hi[BH*SEQ*DEP], g_qh_lo[BH*SEQ*DEP];
__device__ __nv_bfloat16 g_kh_hi[BH*SEQ*DEP], g_kh_lo[BH*SEQ*DEP];
__device__ __nv_bfloat16 g_vt_hi[BH*DEP*SEQ], g_vt_lo[BH*DEP*SEQ];
__device__ __nv_bfloat16 g_at_hi[MTOT*DM],    g_at_lo[MTOT*DM];
__device__ __nv_bfloat16 g_maskb[2u*SEQ*SEQ];   // pre-scaled mask bias (bf16)
__device__ float g_pmax[BH*16*SEQ], g_psum[BH*16*SEQ];
__device__ float g_M[BH*SEQ], g_invZ[BH*SEQ];

// ---------------------------------------------------------------------------
// Helpers
// ---------------------------------------------------------------------------
__device__ __forceinline__ uint32_t smem_u32(const void* p) {
    uint32_t a;
    asm("{ .reg .u64 t; cvta.to.shared.u64 t, %1; cvt.u32.u64 %0, t; }"
        : "=r"(a) : "l"(p));
    return a;
}
#define CP16(s, g)  asm volatile("cp.async.cg.shared.global [%0], [%1], 16;" :: "r"(s), "l"(g))
#define CP_COMMIT() asm volatile("cp.async.commit_group;" ::: "memory")
#define CP_WAIT(n)  asm volatile("cp.async.wait_group %0;" :: "n"(n) : "memory")

#define LDSM4(R, addr) \
    asm volatile("ldmatrix.sync.aligned.m8n8.x4.shared.b16 {%0,%1,%2,%3}, [%4];" \
        : "=r"((R)[0]), "=r"((R)[1]), "=r"((R)[2]), "=r"((R)[3]) : "r"(addr))

#define MMA16816(d, a, b) \
    asm volatile("mma.sync.aligned.m16n8k16.row.col.f32.bf16.bf16.f32 " \
        "{%0,%1,%2,%3}, {%4,%5,%6,%7}, {%8,%9}, {%0,%1,%2,%3};" \
        : "+f"((d)[0]), "+f"((d)[1]), "+f"((d)[2]), "+f"((d)[3]) \
        : "r"((a)[0]), "r"((a)[1]), "r"((a)[2]), "r"((a)[3]), "r"((b)[0]), "r"((b)[1]))

__device__ __forceinline__ uint32_t swz(uint32_t b) { return b ^ ((b >> 3) & 0x70); }

__device__ __forceinline__ uint32_t pack_bf2(float x, float y) {
    __nv_bfloat162 t;
    t.x = __float2bfloat16(x);
    t.y = __float2bfloat16(y);
    return *(uint32_t*)&t;
}

__device__ __forceinline__ void lane_sw(int lane, uint32_t* a_sw, uint32_t* b_sw) {
    #pragma unroll
    for (int kk = 0; kk < 4; kk++) {
        a_sw[kk] = swz(((uint32_t)(lane & 15) << 7) + kk * 32 + ((uint32_t)(lane >> 4) << 4));
        b_sw[kk] = swz((((uint32_t)((lane & 7) | ((lane >> 4) << 3))) << 7)
                       + kk * 32 + (((uint32_t)(lane >> 3) & 1) << 4));
    }
}

// 64-wide K chunk, 3-term split-bf16 MMA. B fragments loaded per 16-col pair.
template<int MF, int NF>
__device__ __forceinline__ void compute_chunk(
    uint32_t AH, uint32_t AL, uint32_t BHb, uint32_t BLb,
    int warpM, int warpN, const uint32_t* a_sw, const uint32_t* b_sw,
    float (*acc)[NF][4])
{
    #pragma unroll
    for (int kk = 0; kk < 4; kk++) {
        uint32_t ah[MF][4], al[MF][4];
        #pragma unroll
        for (int mf = 0; mf < MF; mf++) {
            const uint32_t ro = (uint32_t)(warpM + mf * 16) * 128;
            LDSM4(ah[mf], AH + ro + a_sw[kk]);
            LDSM4(al[mf], AL + ro + a_sw[kk]);
        }
        #pragma unroll
        for (int p = 0; p < NF / 2; p++) {
            const uint32_t ro = (uint32_t)(warpN + p * 16) * 128;
            uint32_t th[4], tl[4];
            LDSM4(th, BHb + ro + b_sw[kk]);
            LDSM4(tl, BLb + ro + b_sw[kk]);
            #pragma unroll
            for (int mf = 0; mf < MF; mf++) {
                MMA16816(acc[mf][2*p],   ah[mf], (th + 0));
                MMA16816(acc[mf][2*p],   ah[mf], (tl + 0));
                MMA16816(acc[mf][2*p],   al[mf], (th + 0));
                MMA16816(acc[mf][2*p+1], ah[mf], (th + 2));
                MMA16816(acc[mf][2*p+1], ah[mf], (tl + 2));
                MMA16816(acc[mf][2*p+1], al[mf], (th + 2));
            }
        }
    }
}

// ---------------------------------------------------------------------------
// q/k/v fp32 -> bf16 hi/lo (z selects tensor)
// ---------------------------------------------------------------------------
__global__ void split4_kernel(const float* q, const float* k, const float* v,
                              __nv_bfloat16* qh, __nv_bfloat16* kh, __nv_bfloat16* vh,
                              __nv_bfloat16* ql, __nv_bfloat16* kl, __nv_bfloat16* vl)
{
    const float* xs[3] = {q, k, v};
    __nv_bfloat16* hs[3] = {qh, kh, vh};
    __nv_bfloat16* ls[3] = {ql, kl, vl};
    const int z = blockIdx.z;
    const int i = blockIdx.x * blockDim.x + threadIdx.x;
    float4 f = ((const float4*)xs[z])[i];
    float vv[4] = {f.x, f.y, f.z, f.w};
    __nv_bfloat16 hb[4], lb[4];
    #pragma unroll
    for (int j = 0; j < 4; j++) {
        hb[j] = __float2bfloat16(vv[j]);
        lb[j] = __float2bfloat16(vv[j] - __bfloat162float(hb[j]));
    }
    *(uint2*)(hs[z] + (size_t)i * 4) = *(uint2*)hb;
    *(uint2*)(ls[z] + (size_t)i * 4) = *(uint2*)lb;
}

// ---------------------------------------------------------------------------
// mask int32 -> bf16 pre-scaled bias (mask * -1e9)
// ---------------------------------------------------------------------------
__global__ void mask_prep_kernel(const int* __restrict__ mask,
                                 __nv_bfloat16* __restrict__ maskb)
{
    const int i = blockIdx.x * blockDim.x + threadIdx.x;
    int4 m = ((const int4*)mask)[i];
    __nv_bfloat16 b[4];
    b[0] = __float2bfloat16((float)m.x * -1e9f);
    b[1] = __float2bfloat16((float)m.y * -1e9f);
    b[2] = __float2bfloat16((float)m.z * -1e9f);
    b[3] = __float2bfloat16((float)m.w * -1e9f);
    *(uint2*)(maskb + (size_t)i * 4) = *(uint2*)b;
}

// ---------------------------------------------------------------------------
// W[k][n] fp32 -> Wt[n][k] bf16 hi/lo; 4 matrices via z
// ---------------------------------------------------------------------------
__global__ void transpose_split_kernel(
    const float* W0, const float* W1, const float* W2, const float* W3,
    __nv_bfloat16* h0, __nv_bfloat16* h1, __nv_bfloat16* h2, __nv_bfloat16* h3,
    __nv_bfloat16* l0, __nv_bfloat16* l1, __nv_bfloat16* l2, __nv_bfloat16* l3)
{
    const float* Ws[4] = {W0, W1, W2, W3};
    __nv_bfloat16* hs[4] = {h0, h1, h2, h3};
    __nv_bfloat16* ls[4] = {l0, l1, l2, l3};
    const int z = blockIdx.z;
    const float* W = Ws[z];
    __nv_bfloat16* hi = hs[z];
    __nv_bfloat16* lo = ls[z];

    __shared__ float s[32][33];
    const int bx = blockIdx.x * 32, by = blockIdx.y * 32;
    const int tx = threadIdx.x, ty = threadIdx.y;  // 32 x 8
    #pragma unroll
    for (int j = 0; j < 4; j++)
        s[ty + j * 8][tx] = W[(size_t)(by + ty + j * 8) * DM + bx + tx];
    __syncthreads();
    #pragma unroll
    for (int j = 0; j < 4; j++) {
        int n = bx + ty + j * 8, k = by + tx;
        float v = s[tx][ty + j * 8];
        __nv_bfloat16 h = __float2bfloat16(v);
        hi[(size_t)n * DM + k] = h;
        lo[(size_t)n * DM + k] = __float2bfloat16(v - __bfloat162float(h));
    }
}

// ---------------------------------------------------------------------------
// Projections: pre-split A (x q/k/v) and B (W). CTA 256x128, warp 64x64.
// ---------------------------------------------------------------------------
__global__ void __launch_bounds__(256, 1)
gemm_proj(const __nv_bfloat16* __restrict__ xqh, const __nv_bfloat16* __restrict__ xkh,
          const __nv_bfloat16* __restrict__ xvh,
          const __nv_bfloat16* __restrict__ xql, const __nv_bfloat16* __restrict__ xkl,
          const __nv_bfloat16* __restrict__ xvl,
          const __nv_bfloat16* __restrict__ wqh, const __nv_bfloat16* __restrict__ wkh,
          const __nv_bfloat16* __restrict__ wvh,
          const __nv_bfloat16* __restrict__ wql, const __nv_bfloat16* __restrict__ wkl,
          const __nv_bfloat16* __restrict__ wvl,
          const float* __restrict__ bqp, const float* __restrict__ bkp,
          const float* __restrict__ bvp,
          __nv_bfloat16* __restrict__ qhh, __nv_bfloat16* __restrict__ khh,
          __nv_bfloat16* __restrict__ vth,
          __nv_bfloat16* __restrict__ qhl, __nv_bfloat16* __restrict__ khl,
          __nv_bfloat16* __restrict__ vtl)
{
    extern __shared__ char smem[];
    const uint32_t sb = smem_u32(smem);
    const int tid = threadIdx.x, lane = tid & 31, wid = tid >> 5;
    const int bn = blockIdx.x * 128, bm = blockIdx.y * 256, z = blockIdx.z;

    const __nv_bfloat16* Ahs[3] = {xqh, xkh, xvh};
    const __nv_bfloat16* Als[3] = {xql, xkl, xvl};
    const __nv_bfloat16* Bhs[3] = {wqh, wkh, wvh};
    const __nv_bfloat16* Bls[3] = {wql, wkl, wvl};
    const float* bias_s[3] = {bqp, bkp, bvp};
    __nv_bfloat16* ohs[3] = {qhh, khh, vth};
    __nv_bfloat16* ols[3] = {qhl, khl, vtl};
    const __nv_bfloat16* Ah = Ahs[z];
    const __nv_bfloat16* Al = Als[z];
    const __nv_bfloat16* Bh = Bhs[z];
    const __nv_bfloat16* Bl = Bls[z];
    const float* bias = bias_s[z];
    __nv_bfloat16* oh = ohs[z];
    __nv_bfloat16* ol = ols[z];

    constexpr uint32_t AOFF = 0, ABUF = 65536;        // hi@0 lo@32768, x2
    constexpr uint32_t BOFF = 131072, BBUF = 32768;   // hi@0 lo@16384, x2
    const int warpM = (wid >> 1) * 64, warpN = (wid & 1) * 64;

    uint32_t a_sw[4], b_sw[4];
    lane_sw(lane, a_sw, b_sw);

    float acc[4][8][4];
    #pragma unroll
    for (int i = 0; i < 4; i++)
        #pragma unroll
        for (int j = 0; j < 8; j++)
            #pragma unroll
            for (int r = 0; r < 4; r++) acc[i][j][r] = 0.f;

    auto issueAB = [&](int c, int buf) {
        const int k0 = c << 6;
        #pragma unroll
        for (int i = 0; i < 8; i++) {
            int u = tid + i * 256, row = u >> 3, c8 = u & 7;
            uint32_t d = swz((uint32_t)row * 128 + c8 * 16);
            const size_t src = (size_t)(bm + row) * DM + k0 + c8 * 8;
            CP16(sb + AOFF + buf * ABUF + d,         Ah + src);
            CP16(sb + AOFF + buf * ABUF + 32768 + d, Al + src);
        }
        #pragma unroll
        for (int i = 0; i < 4; i++) {
            int u = tid + i * 256, row = u >> 3, c8 = u & 7;
            uint32_t d = swz((uint32_t)row * 128 + c8 * 16);
            const size_t src = (size_t)(bn + row) * DM + k0 + c8 * 8;
            CP16(sb + BOFF + buf * BBUF + d,         Bh + src);
            CP16(sb + BOFF + buf * BBUF + 16384 + d, Bl + src);
        }
        CP_COMMIT();
    };

    const int C = DM >> 6;  // 16
    issueAB(0, 0);
    for (int c = 0; c < C; c++) {
        CP_WAIT(0);
        __syncthreads();
        if (c + 1 < C) issueAB(c + 1, (c + 1) & 1);
        compute_chunk<4, 8>(sb + AOFF + (c & 1) * ABUF,
                            sb + AOFF + (c & 1) * ABUF + 32768,
                            sb + BOFF + (c & 1) * BBUF,
                            sb + BOFF + (c & 1) * BBUF + 16384,
                            warpM, warpN, a_sw, b_sw, acc);
    }

    // epilogue
    const int rr = lane >> 2, cc = (lane & 3) * 2;
    #pragma unroll
    for (int mf = 0; mf < 4; mf++)
        #pragma unroll
        for (int nf = 0; nf < 8; nf++) {
            const int n = bn + warpN + nf * 8 + cc;
            #pragma unroll
            for (int half = 0; half < 2; half++) {
                const int m = bm + warpM + mf * 16 + rr + half * 8;
                const float x = acc[mf][nf][half*2]     + bias[n];
                const float y = acc[mf][nf][half*2 + 1] + bias[n + 1];
                const int b = m >> 11, l = m & 2047;
                if (z < 2) {  // head layout [bh][l][d]
                    const int h = n >> 6, d = n & 63;
                    const size_t o = ((size_t)(b * NH + h) * SEQ + l) * DEP + d;
                    const float hx = __bfloat162float(__float2bfloat16(x));
                    const float hy = __bfloat162float(__float2bfloat16(y));
                    *(uint32_t*)(oh + o) = pack_bf2(x, y);
                    *(uint32_t*)(ol + o) = pack_bf2(x - hx, y - hy);
                } else {      // V transposed [bh][d][l]
                    #pragma unroll
                    for (int j = 0; j < 2; j++) {
                        const int nn = n + j;
                        const int h = nn >> 6, d = nn & 63;
                        const float v = j ? y : x;
                        const __nv_bfloat16 hv = __float2bfloat16(v);
                        const size_t o = ((size_t)(b * NH + h) * DEP + d) * SEQ + l;
                        oh[o] = hv;
                        ol[o] = __float2bfloat16(v - __bfloat162float(hv));
                    }
                }
            }
        }
}

// ---------------------------------------------------------------------------
// Scores: CTA 128x128, 128 threads (4 warps of 64x64) -> 2 CTAs/SM.
// Single-shot K=64. bf16 mask bias. Writes raw masked S fp32 + partials.
// ---------------------------------------------------------------------------
__global__ void __launch_bounds__(128, 2)
gemm_scores(const __nv_bfloat16* __restrict__ Ahi, const __nv_bfloat16* __restrict__ Alo,
            const __nv_bfloat16* __restrict__ Bhi, const __nv_bfloat16* __restrict__ Blo,
            const __nv_bfloat16* __restrict__ maskb, float* __restrict__ S,
            float* __restrict__ pmax, float* __restrict__ psum)
{
    extern __shared__ char smem[];
    const uint32_t sb = smem_u32(smem);
    const int tid = threadIdx.x, lane = tid & 31, wid = tid >> 5;
    const int bn = blockIdx.x * 128, bm = blockIdx.y * 128, z = blockIdx.z;

    const __nv_bfloat16* Ah = Ahi + (size_t)z * SEQ * DEP;
    const __nv_bfloat16* Al = Alo + (size_t)z * SEQ * DEP;
    const __nv_bfloat16* Bh = Bhi + (size_t)z * SEQ * DEP;
    const __nv_bfloat16* Bl = Blo + (size_t)z * SEQ * DEP;

    const int warpM = (wid >> 1) * 64, warpN = (wid & 1) * 64;
    uint32_t a_sw[4], b_sw[4];
    lane_sw(lane, a_sw, b_sw);

    // A hi@0 lo@16384; B hi@32768 lo@49152
    #pragma unroll
    for (int i = 0; i < 8; i++) {
        int u = tid + i * 128, row = u >> 3, c8 = u & 7;
        uint32_t d = swz((uint32_t)row * 128 + c8 * 16);
        const size_t sa = (size_t)(bm + row) * DEP + c8 * 8;
        const size_t sbo = (size_t)(bn + row) * DEP + c8 * 8;
        CP16(sb + d,         Ah + sa);
        CP16(sb + 16384 + d, Al + sa);
        CP16(sb + 32768 + d, Bh + sbo);
        CP16(sb + 49152 + d, Bl + sbo);
    }
    CP_COMMIT();
    CP_WAIT(0);
    __syncthreads();

    float acc[4][8][4];
    #pragma unroll
    for (int i = 0; i < 4; i++)
        #pragma unroll
        for (int j = 0; j < 8; j++)
            #pragma unroll
            for (int r = 0; r < 4; r++) acc[i][j][r] = 0.f;

    compute_chunk<4, 8>(sb, sb + 16384, sb + 32768, sb + 49152,
                        warpM, warpN, a_sw, b_sw, acc);

    // scale + mask, write S, accumulate partials
    const int rr = lane >> 2, cc = (lane & 3) * 2;
    float* smax = (float*)(smem + 65536);   // [2][128]
    float* ssum = smax + 256;               // [2][128]

    #pragma unroll
    for (int mf = 0; mf < 4; mf++)
        #pragma unroll
        for (int half = 0; half < 2; half++) {
            const int r = warpM + mf * 16 + rr + half * 8;
            const int m = bm + r;
            const __nv_bfloat16* mrow = maskb + ((size_t)(z >> 4) * SEQ + m) * SEQ;
            float mx = -3.4e38f;
            #pragma unroll
            for (int nf = 0; nf < 8; nf++) {
                const int n = bn + warpN + nf * 8 + cc;
                uint32_t mraw = *(const uint32_t*)(mrow + n);
                __nv_bfloat162 mv = *(__nv_bfloat162*)&mraw;
                float x = acc[mf][nf][half*2]     * 0.125f + __bfloat162float(mv.x);
                float y = acc[mf][nf][half*2 + 1] * 0.125f + __bfloat162float(mv.y);
                acc[mf][nf][half*2] = x; acc[mf][nf][half*2+1] = y;
                float2 v = {x, y};
                *(float2*)(S + ((size_t)z * SEQ + m) * SEQ + n) = v;
                mx = fmaxf(mx, fmaxf(x, y));
            }
            mx = fmaxf(mx, __shfl_xor_sync(0xffffffffu, mx, 1));
            mx = fmaxf(mx, __shfl_xor_sync(0xffffffffu, mx, 2));
            float sm = 0.f;
            #pragma unroll
            for (int nf = 0; nf < 8; nf++) {
                sm += __expf(acc[mf][nf][half*2]   - mx);
                sm += __expf(acc[mf][nf][half*2+1] - mx);
            }
            sm += __shfl_xor_sync(0xffffffffu, sm, 1);
            sm += __shfl_xor_sync(0xffffffffu, sm, 2);
            if ((lane & 3) == 0) {
                smax[(wid & 1) * 128 + r] = mx;
                ssum[(wid & 1) * 128 + r] = sm;
            }
        }
    __syncthreads();
    {
        float m0 = smax[tid], m1 = smax[128 + tid];
        float M = fmaxf(m0, m1);
        float Zp = ssum[tid] * __expf(m0 - M) + ssum[128 + tid] * __expf(m1 - M);
        const size_t o = ((size_t)z * 16 + blockIdx.x) * SEQ + bm + tid;
        pmax[o] = M;
        psum[o] = Zp;
    }
}

// ---------------------------------------------------------------------------
// Combine partials (16 tiles) -> row max M and invZ
// ---------------------------------------------------------------------------
__global__ void __launch_bounds__(256)
combine_kernel(const float* __restrict__ pmax, const float* __restrict__ psum,
               float* __restrict__ gM, float* __restrict__ gInvZ)
{
    const int R = blockIdx.x * 256 + threadIdx.x;   // 0..65535
    const int bh = R >> 11, m = R & 2047;
    float mx[16];
    float M = -3.4e38f;
    #pragma unroll
    for (int t = 0; t < 16; t++) {
        mx[t] = pmax[((size_t)bh * 16 + t) * SEQ + m];
        M = fmaxf(M, mx[t]);
    }
    float Z = 0.f;
    #pragma unroll
    for (int t = 0; t < 16; t++)
        Z += psum[((size_t)bh * 16 + t) * SEQ + m] * __expf(mx[t] - M);
    gM[R] = M;
    gInvZ[R] = 1.0f / Z;
}

// ---------------------------------------------------------------------------
// AV: CTA 256x64, warp 64x32 (MF=4, NF=4). A = raw S fp32 -> finalize
// w = exp(s-M)*invZ (write in place), split hi/lo, MMA vs pre-split V^T.
// ---------------------------------------------------------------------------
__global__ void __launch_bounds__(256, 1)
gemm_av(float* __restrict__ S,
        const __nv_bfloat16* __restrict__ Bhi, const __nv_bfloat16* __restrict__ Blo,
        const float* __restrict__ gM, const float* __restrict__ gInvZ,
        __nv_bfloat16* __restrict__ oh, __nv_bfloat16* __restrict__ ol)
{
    extern __shared__ char smem[];
    const uint32_t sb = smem_u32(smem);
    const int tid = threadIdx.x, lane = tid & 31, wid = tid >> 5;
    const int bm = blockIdx.y * 256, z = blockIdx.z;

    float* Sp = S + (size_t)z * SEQ * SEQ;
    const __nv_bfloat16* Bh = Bhi + (size_t)z * DEP * SEQ;
    const __nv_bfloat16* Bl = Blo + (size_t)z * DEP * SEQ;
    const int Rbase = z * SEQ + bm;

    constexpr uint32_t AOFF = 0, ABUF = 65536;      // hi@0 lo@32768, x2
    constexpr uint32_t BOFF = 131072, BBUF = 16384; // hi@0 lo@8192, x3
    const int warpM = (wid >> 1) * 64, warpN = (wid & 1) * 32;

    uint32_t a_sw[4], b_sw[4];
    lane_sw(lane, a_sw, b_sw);

    float acc[4][4][4];
    #pragma unroll
    for (int i = 0; i < 4; i++)
        #pragma unroll
        for (int j = 0; j < 4; j++)
            #pragma unroll
            for (int r = 0; r < 4; r++) acc[i][j][r] = 0.f;

    float4 sv[16];
    auto ldgA = [&](int c) {
        const int k0 = c << 6;
        #pragma unroll
        for (int j = 0; j < 16; j++) {
            int g = j * 256 + tid, row = g >> 4, c4 = g & 15;
            sv[j] = *(const float4*)(Sp + (size_t)(bm + row) * SEQ + k0 + c4 * 4);
        }
    };
    auto convA = [&](int c, int buf) {
        const int k0 = c << 6;
        #pragma unroll
        for (int j = 0; j < 16; j++) {
            int g = j * 256 + tid, row = g >> 4, c4 = g & 15;
            const float M = gM[Rbase + row], iZ = gInvZ[Rbase + row];
            float vv[4];
            vv[0] = __expf(sv[j].x - M) * iZ;
            vv[1] = __expf(sv[j].y - M) * iZ;
            vv[2] = __expf(sv[j].z - M) * iZ;
            vv[3] = __expf(sv[j].w - M) * iZ;
            *(float4*)(Sp + (size_t)(bm + row) * SEQ + k0 + c4 * 4) =
                make_float4(vv[0], vv[1], vv[2], vv[3]);
            float h[4];
            #pragma unroll
            for (int t = 0; t < 4; t++) h[t] = __bfloat162float(__float2bfloat16(vv[t]));
            uint2 H = { pack_bf2(vv[0], vv[1]), pack_bf2(vv[2], vv[3]) };
            uint2 L = { pack_bf2(vv[0]-h[0], vv[1]-h[1]), pack_bf2(vv[2]-h[2], vv[3]-h[3]) };
            uint32_t d = swz((uint32_t)row * 128 + c4 * 8);
            *(uint2*)(smem + AOFF + buf * ABUF + d)         = H;
            *(uint2*)(smem + AOFF + buf * ABUF + 32768 + d) = L;
        }
    };
    auto issueB = [&](int c, int buf) {
        const int k0 = c << 6;
        #pragma unroll
        for (int i = 0; i < 2; i++) {
            int u = tid + i * 256, row = u >> 3, c8 = u & 7;
            uint32_t d = swz((uint32_t)row * 128 + c8 * 16);
            const size_t src = (size_t)row * SEQ + k0 + c8 * 8;
            CP16(sb + BOFF + buf * BBUF + d,        Bh + src);
            CP16(sb + BOFF + buf * BBUF + 8192 + d, Bl + src);
        }
        CP_COMMIT();
    };

    const int C = SEQ >> 6;  // 32
    ldgA(0);
    issueB(0, 0);
    issueB(1, 1);
    convA(0, 0);
    ldgA(1);
    for (int c = 0; c < C; c++) {
        if (c + 1 < C) CP_WAIT(1); else CP_WAIT(0);
        __syncthreads();
        if (c + 2 < C) issueB(c + 2, (c + 2) % 3);
        compute_chunk<4, 4>(sb + AOFF + (c & 1) * ABUF,
                            sb + AOFF + (c & 1) * ABUF + 32768,
                            sb + BOFF + (c % 3) * BBUF,
                            sb + BOFF + (c % 3) * BBUF + 8192,
                            warpM, warpN, a_sw, b_sw, acc);
        if (c + 1 < C) {
            convA(c + 1, (c + 1) & 1);
            if (c + 2 < C) ldgA(c + 2);
        }
    }

    // epilogue -> at hi/lo [b*SEQ+m][h*DEP+n]
    const int rr = lane >> 2, cc = (lane & 3) * 2;
    #pragma unroll
    for (int mf = 0; mf < 4; mf++)
        #pragma unroll
        for (int nf = 0; nf < 4; nf++) {
            const int n = warpN + nf * 8 + cc;
            #pragma unroll
            for (int half = 0; half < 2; half++) {
                const int m = bm + warpM + mf * 16 + rr + half * 8;
                const float x = acc[mf][nf][half*2];
                const float y = acc[mf][nf][half*2+1];
                const size_t o = ((size_t)((z >> 4) * SEQ + m)) * DM + (z & 15) * DEP + n;
                const float hx = __bfloat162float(__float2bfloat16(x));
                const float hy = __bfloat162float(__float2bfloat16(y));
                *(uint32_t*)(oh + o) = pack_bf2(x, y);
                *(uint32_t*)(ol + o) = pack_bf2(x - hx, y - hy);
            }
        }
}

// ---------------------------------------------------------------------------
// Output projection: CTA 256x128, warp 64x64, pre-split A and B.
// ---------------------------------------------------------------------------
__global__ void __launch_bounds__(256, 1)
gemm_out(const __nv_bfloat16* __restrict__ Ahi, const __nv_bfloat16* __restrict__ Alo,
         const __nv_bfloat16* __restrict__ Bhi, const __nv_bfloat16* __restrict__ Blo,
         const float* __restrict__ bias, float* __restrict__ outf)
{
    extern __shared__ char smem[];
    const uint32_t sb = smem_u32(smem);
    const int tid = threadIdx.x, lane = tid & 31, wid = tid >> 5;
    const int bn = blockIdx.x * 128, bm = blockIdx.y * 256;

    constexpr uint32_t AOFF = 0, ABUF = 65536;        // hi@0 lo@32768, x2
    constexpr uint32_t BOFF = 131072, BBUF = 32768;   // hi@0 lo@16384, x2
    const int warpM = (wid >> 1) * 64, warpN = (wid & 1) * 64;

    uint32_t a_sw[4], b_sw[4];
    lane_sw(lane, a_sw, b_sw);

    float acc[4][8][4];
    #pragma unroll
    for (int i = 0; i < 4; i++)
        #pragma unroll
        for (int j = 0; j < 8; j++)
            #pragma unroll
            for (int r = 0; r < 4; r++) acc[i][j][r] = 0.f;

    auto issueAB = [&](int c, int buf) {
        const int k0 = c << 6;
        #pragma unroll
        for (int i = 0; i < 8; i++) {
            int u = tid + i * 256, row = u >> 3, c8 = u & 7;
            uint32_t d = swz((uint32_t)row * 128 + c8 * 16);
            const size_t src = (size_t)(bm + row) * DM + k0 + c8 * 8;
            CP16(sb + AOFF + buf * ABUF + d,         Ahi + src);
            CP16(sb + AOFF + buf * ABUF + 32768 + d, Alo + src);
        }
        #pragma unroll
        for (int i = 0; i < 4; i++) {
            int u = tid + i * 256, row = u >> 3, c8 = u & 7;
            uint32_t d = swz((uint32_t)row * 128 + c8 * 16);
            const size_t src = (size_t)(bn + row) * DM + k0 + c8 * 8;
            CP16(sb + BOFF + buf * BBUF + d,         Bhi + src);
            CP16(sb + BOFF + buf * BBUF + 16384 + d, Blo + src);
        }
        CP_COMMIT();
    };

    const int C = DM >> 6;  // 16
    issueAB(0, 0);
    for (int c = 0; c < C; c++) {
        CP_WAIT(0);
        __syncthreads();
        if (c + 1 < C) issueAB(c + 1, (c + 1) & 1);
        compute_chunk<4, 8>(sb + AOFF + (c & 1) * ABUF,
                            sb + AOFF + (c & 1) * ABUF + 32768,
                            sb + BOFF + (c & 1) * BBUF,
                            sb + BOFF + (c & 1) * BBUF + 16384,
                            warpM, warpN, a_sw, b_sw, acc);
    }

    const int rr = lane >> 2, cc = (lane & 3) * 2;
    #pragma unroll
    for (int mf = 0; mf < 4; mf++)
        #pragma unroll
        for (int nf = 0; nf < 8; nf++) {
            const int n = bn + warpN + nf * 8 + cc;
            #pragma unroll
            for (int half = 0; half < 2; half++) {
                const int m = bm + warpM + mf * 16 + rr + half * 8;
                float2 v = { acc[mf][nf][half*2] + bias[n],
                             acc[mf][nf][half*2+1] + bias[n+1] };
                *(float2*)(outf + (size_t)m * DM + n) = v;
            }
        }
}

// ---------------------------------------------------------------------------
extern "C" void kernel_launch(void* const* d_in, const int* in_sizes, int n_in,
                              void* d_out, int out_size)
{
    const float* q    = (const float*)d_in[0];
    const float* k    = (const float*)d_in[1];
    const float* v    = (const float*)d_in[2];
    const int*   mask = (const int*)  d_in[3];
    const float* Wq   = (const float*)d_in[4];
    const float* bq   = (const float*)d_in[5];
    const float* Wk   = (const float*)d_in[6];
    const float* bk   = (const float*)d_in[7];
    const float* Wv   = (const float*)d_in[8];
    const float* bv   = (const float*)d_in[9];
    const float* Wo   = (const float*)d_in[10];
    const float* bo   = (const float*)d_in[11];

    float* out   = (float*)d_out;
    float* attnW = out + (size_t)MTOT * DM;

    __nv_bfloat16 *xqh,*xql,*xkh,*xkl,*xvh,*xvl;
    __nv_bfloat16 *wqh,*wql,*wkh,*wkl,*wvh,*wvl,*woh,*wol;
    __nv_bfloat16 *qhh,*qhl,*khh,*khl,*vth,*vtl,*ath,*atl,*maskb;
    float *pmax,*psum,*gM,*gZ;
    cudaGetSymbolAddress((void**)&xqh, g_xq_hi); cudaGetSymbolAddress((void**)&xql, g_xq_lo);
    cudaGetSymbolAddress((void**)&xkh, g_xk_hi); cudaGetSymbolAddress((void**)&xkl, g_xk_lo);
    cudaGetSymbolAddress((void**)&xvh, g_xv_hi); cudaGetSymbolAddress((void**)&xvl, g_xv_lo);
    cudaGetSymbolAddress((void**)&wqh, g_wq_hi); cudaGetSymbolAddress((void**)&wql, g_wq_lo);
    cudaGetSymbolAddress((void**)&wkh, g_wk_hi); cudaGetSymbolAddress((void**)&wkl, g_wk_lo);
    cudaGetSymbolAddress((void**)&wvh, g_wv_hi); cudaGetSymbolAddress((void**)&wvl, g_wv_lo);
    cudaGetSymbolAddress((void**)&woh, g_wo_hi); cudaGetSymbolAddress((void**)&wol, g_wo_lo);
    cudaGetSymbolAddress((void**)&qhh, g_qh_hi); cudaGetSymbolAddress((void**)&qhl, g_qh_lo);
    cudaGetSymbolAddress((void**)&khh, g_kh_hi); cudaGetSymbolAddress((void**)&khl, g_kh_lo);
    cudaGetSymbolAddress((void**)&vth, g_vt_hi); cudaGetSymbolAddress((void**)&vtl, g_vt_lo);
    cudaGetSymbolAddress((void**)&ath, g_at_hi); cudaGetSymbolAddress((void**)&atl, g_at_lo);
    cudaGetSymbolAddress((void**)&maskb, g_maskb);
    cudaGetSymbolAddress((void**)&pmax, g_pmax); cudaGetSymbolAddress((void**)&psum, g_psum);
    cudaGetSymbolAddress((void**)&gM, g_M);      cudaGetSymbolAddress((void**)&gZ, g_invZ);

    const int SM_BIG = 2 * 65536 + 2 * 32768;       // 196608
    const int SM_SC  = 65536 + 2048;                // 67584
    const int SM_AV  = 2 * 65536 + 3 * 16384;       // 180224
    cudaFuncSetAttribute(gemm_proj,   cudaFuncAttributeMaxDynamicSharedMemorySize, SM_BIG);
    cudaFuncSetAttribute(gemm_scores, cudaFuncAttributeMaxDynamicSharedMemorySize, SM_SC);
    cudaFuncSetAttribute(gemm_av,     cudaFuncAttributeMaxDynamicSharedMemorySize, SM_AV);
    cudaFuncSetAttribute(gemm_out,    cudaFuncAttributeMaxDynamicSharedMemorySize, SM_BIG);

    // 1. input splits + mask prep + weight transpose/splits
    split4_kernel<<<dim3(MTOT * DM / 4 / 256, 1, 3), 256>>>(
        q, k, v, xqh, xkh, xvh, xql, xkl, xvl);
    mask_prep_kernel<<<2u * SEQ * SEQ / 4 / 256, 256>>>(mask, maskb);
    transpose_split_kernel<<<dim3(32, 32, 4), dim3(32, 8)>>>(
        Wq, Wk, Wv, Wo, wqh, wkh, wvh, woh, wql, wkl, wvl, wol);

    // 2. Q/K/V projections
    gemm_proj<<<dim3(8, 16, 3), 256, SM_BIG>>>(
        xqh, xkh, xvh, xql, xkl, xvl, wqh, wkh, wvh, wql, wkl, wvl,
        bq, bk, bv, qhh, khh, vth, qhl, khl, vtl);

    // 3. scores + mask + softmax partials (128-thread CTAs, 2/SM)
    gemm_scores<<<dim3(16, 16, BH), 128, SM_SC>>>(
        qhh, qhl, khh, khl, maskb, attnW, pmax, psum);

    // 4. combine partials
    combine_kernel<<<BH * SEQ / 256, 256>>>(pmax, psum, gM, gZ);

    // 5. AV with fused softmax finalize (CTA 256x64)
    gemm_av<<<dim3(1, 8, BH), 256, SM_AV>>>(
        attnW, vth, vtl, gM, gZ, ath, atl);

    // 6. output projection
    gemm_out<<<dim3(8, 16, 1), 256, SM_BIG>>>(ath, atl, woh, wol, bo, out);
}

// round 10
// speedup vs baseline: 1.7003x; 1.0500x over previous
#include <cuda_runtime.h>
#include <cuda_bf16.h>
#include <cstdint>

#define SEQ   2048
#define DM    1024
#define NH    16
#define DEP   64
#define MTOT  4096
#define BH    32

// ---------------------------------------------------------------------------
// Device scratch (allocation-free). q/k/v consolidated for z-indexing.
// ---------------------------------------------------------------------------
__device__ __nv_bfloat16 g_x_hi[3u*MTOT*DM],  g_x_lo[3u*MTOT*DM];
__device__ __nv_bfloat16 g_wqkv_hi[3u*DM*DM], g_wqkv_lo[3u*DM*DM];
__device__ __nv_bfloat16 g_wo_hi[DM*DM],      g_wo_lo[DM*DM];
__device__ float         g_bias3[3*DM];
__device__ __nv_bfloat16 g_qkh_hi[2u*BH*SEQ*DEP], g_qkh_lo[2u*BH*SEQ*DEP];
__device__ __nv_bfloat16 g_vt_hi[BH*DEP*SEQ],     g_vt_lo[BH*DEP*SEQ];
__device__ __nv_bfloat16 g_at_hi[MTOT*DM],        g_at_lo[MTOT*DM];
__device__ __nv_bfloat16 g_maskb[2u*SEQ*SEQ];
__device__ float g_pmax[BH*16*SEQ], g_psum[BH*16*SEQ];
__device__ float g_M[BH*SEQ], g_invZ[BH*SEQ];

// ---------------------------------------------------------------------------
// Helpers
// ---------------------------------------------------------------------------
__device__ __forceinline__ uint32_t smem_u32(const void* p) {
    uint32_t a;
    asm("{ .reg .u64 t; cvta.to.shared.u64 t, %1; cvt.u32.u64 %0, t; }"
        : "=r"(a) : "l"(p));
    return a;
}
#define CP16(s, g)  asm volatile("cp.async.cg.shared.global [%0], [%1], 16;" :: "r"(s), "l"(g))
#define CP_COMMIT() asm volatile("cp.async.commit_group;" ::: "memory")
#define CP_WAIT(n)  asm volatile("cp.async.wait_group %0;" :: "n"(n) : "memory")

#define LDSM4(R, addr) \
    asm volatile("ldmatrix.sync.aligned.m8n8.x4.shared.b16 {%0,%1,%2,%3}, [%4];" \
        : "=r"((R)[0]), "=r"((R)[1]), "=r"((R)[2]), "=r"((R)[3]) : "r"(addr))

#define MMA16816(d, a, b) \
    asm volatile("mma.sync.aligned.m16n8k16.row.col.f32.bf16.bf16.f32 " \
        "{%0,%1,%2,%3}, {%4,%5,%6,%7}, {%8,%9}, {%0,%1,%2,%3};" \
        : "+f"((d)[0]), "+f"((d)[1]), "+f"((d)[2]), "+f"((d)[3]) \
        : "r"((a)[0]), "r"((a)[1]), "r"((a)[2]), "r"((a)[3]), "r"((b)[0]), "r"((b)[1]))

__device__ __forceinline__ uint32_t swz(uint32_t b) { return b ^ ((b >> 3) & 0x70); }

__device__ __forceinline__ uint32_t pack_bf2(float x, float y) {
    __nv_bfloat162 t;
    t.x = __float2bfloat16(x);
    t.y = __float2bfloat16(y);
    return *(uint32_t*)&t;
}

__device__ __forceinline__ void lane_sw(int lane, uint32_t* a_sw, uint32_t* b_sw) {
    #pragma unroll
    for (int kk = 0; kk < 4; kk++) {
        a_sw[kk] = swz(((uint32_t)(lane & 15) << 7) + kk * 32 + ((uint32_t)(lane >> 4) << 4));
        b_sw[kk] = swz((((uint32_t)((lane & 7) | ((lane >> 4) << 3))) << 7)
                       + kk * 32 + (((uint32_t)(lane >> 3) & 1) << 4));
    }
}

// 64-wide K chunk, 3-term split-bf16 MMA. B fragments loaded per 16-col pair.
template<int MF, int NF>
__device__ __forceinline__ void compute_chunk(
    uint32_t AH, uint32_t AL, uint32_t BHb, uint32_t BLb,
    int warpM, int warpN, const uint32_t* a_sw, const uint32_t* b_sw,
    float (*acc)[NF][4])
{
    #pragma unroll
    for (int kk = 0; kk < 4; kk++) {
        uint32_t ah[MF][4], al[MF][4];
        #pragma unroll
        for (int mf = 0; mf < MF; mf++) {
            const uint32_t ro = (uint32_t)(warpM + mf * 16) * 128;
            LDSM4(ah[mf], AH + ro + a_sw[kk]);
            LDSM4(al[mf], AL + ro + a_sw[kk]);
        }
        #pragma unroll
        for (int p = 0; p < NF / 2; p++) {
            const uint32_t ro = (uint32_t)(warpN + p * 16) * 128;
            uint32_t th[4], tl[4];
            LDSM4(th, BHb + ro + b_sw[kk]);
            LDSM4(tl, BLb + ro + b_sw[kk]);
            #pragma unroll
            for (int mf = 0; mf < MF; mf++) {
                MMA16816(acc[mf][2*p],   ah[mf], (th + 0));
                MMA16816(acc[mf][2*p],   ah[mf], (tl + 0));
                MMA16816(acc[mf][2*p],   al[mf], (th + 0));
                MMA16816(acc[mf][2*p+1], ah[mf], (th + 2));
                MMA16816(acc[mf][2*p+1], ah[mf], (tl + 2));
                MMA16816(acc[mf][2*p+1], al[mf], (th + 2));
            }
        }
    }
}

// ---------------------------------------------------------------------------
// q/k/v fp32 -> bf16 hi/lo into consolidated buffer (z offset)
// ---------------------------------------------------------------------------
__global__ void split4_kernel(const float* q, const float* k, const float* v,
                              __nv_bfloat16* xh, __nv_bfloat16* xl)
{
    const float* xs[3] = {q, k, v};
    const int z = blockIdx.z;
    const int i = blockIdx.x * blockDim.x + threadIdx.x;
    float4 f = ((const float4*)xs[z])[i];
    float vv[4] = {f.x, f.y, f.z, f.w};
    __nv_bfloat16 hb[4], lb[4];
    #pragma unroll
    for (int j = 0; j < 4; j++) {
        hb[j] = __float2bfloat16(vv[j]);
        lb[j] = __float2bfloat16(vv[j] - __bfloat162float(hb[j]));
    }
    const size_t o = (size_t)z * MTOT * DM + (size_t)i * 4;
    *(uint2*)(xh + o) = *(uint2*)hb;
    *(uint2*)(xl + o) = *(uint2*)lb;
}

// ---------------------------------------------------------------------------
// mask int32 -> bf16 pre-scaled bias, + bias pack (block 0 range)
// ---------------------------------------------------------------------------
__global__ void mask_prep_kernel(const int* __restrict__ mask,
                                 __nv_bfloat16* __restrict__ maskb,
                                 const float* bq, const float* bk, const float* bv,
                                 float* b3)
{
    const int i = blockIdx.x * blockDim.x + threadIdx.x;
    int4 m = ((const int4*)mask)[i];
    __nv_bfloat16 b[4];
    b[0] = __float2bfloat16((float)m.x * -1e9f);
    b[1] = __float2bfloat16((float)m.y * -1e9f);
    b[2] = __float2bfloat16((float)m.z * -1e9f);
    b[3] = __float2bfloat16((float)m.w * -1e9f);
    *(uint2*)(maskb + (size_t)i * 4) = *(uint2*)b;
    if (i < 3 * DM) {
        const float* s[3] = {bq, bk, bv};
        b3[i] = s[i >> 10][i & 1023];
    }
}

// ---------------------------------------------------------------------------
// W[k][n] fp32 -> Wt[n][k] bf16 hi/lo; q/k/v into consolidated, Wo separate
// ---------------------------------------------------------------------------
__global__ void transpose_split_kernel(
    const float* W0, const float* W1, const float* W2, const float* W3,
    __nv_bfloat16* wqkv_hi, __nv_bfloat16* wqkv_lo,
    __nv_bfloat16* wo_hi, __nv_bfloat16* wo_lo)
{
    const float* Ws[4] = {W0, W1, W2, W3};
    const int z = blockIdx.z;
    const float* W = Ws[z];
    __nv_bfloat16* hi = (z < 3) ? (wqkv_hi + (size_t)z * DM * DM) : wo_hi;
    __nv_bfloat16* lo = (z < 3) ? (wqkv_lo + (size_t)z * DM * DM) : wo_lo;

    __shared__ float s[32][33];
    const int bx = blockIdx.x * 32, by = blockIdx.y * 32;
    const int tx = threadIdx.x, ty = threadIdx.y;  // 32 x 8
    #pragma unroll
    for (int j = 0; j < 4; j++)
        s[ty + j * 8][tx] = W[(size_t)(by + ty + j * 8) * DM + bx + tx];
    __syncthreads();
    #pragma unroll
    for (int j = 0; j < 4; j++) {
        int n = bx + ty + j * 8, k = by + tx;
        float v = s[tx][ty + j * 8];
        __nv_bfloat16 h = __float2bfloat16(v);
        hi[(size_t)n * DM + k] = h;
        lo[(size_t)n * DM + k] = __float2bfloat16(v - __bfloat162float(h));
    }
}

// ---------------------------------------------------------------------------
// Projections: consolidated buffers, 9 pointer params. CTA 256x128, warp 64x64.
// ---------------------------------------------------------------------------
__global__ void __launch_bounds__(256, 1)
gemm_proj(const __nv_bfloat16* __restrict__ xh, const __nv_bfloat16* __restrict__ xl,
          const __nv_bfloat16* __restrict__ wh, const __nv_bfloat16* __restrict__ wl,
          const float* __restrict__ b3,
          __nv_bfloat16* __restrict__ qkh, __nv_bfloat16* __restrict__ qkl,
          __nv_bfloat16* __restrict__ vth, __nv_bfloat16* __restrict__ vtl)
{
    extern __shared__ char smem[];
    const uint32_t sb = smem_u32(smem);
    const int tid = threadIdx.x, lane = tid & 31, wid = tid >> 5;
    const int bn = blockIdx.x * 128, bm = blockIdx.y * 256, z = blockIdx.z;

    const __nv_bfloat16* Ah = xh + (size_t)z * MTOT * DM;
    const __nv_bfloat16* Al = xl + (size_t)z * MTOT * DM;
    const __nv_bfloat16* Bh = wh + (size_t)z * DM * DM;
    const __nv_bfloat16* Bl = wl + (size_t)z * DM * DM;
    const float* bias = b3 + z * DM;
    __nv_bfloat16* oh = (z < 2) ? (qkh + (size_t)z * BH * SEQ * DEP) : vth;
    __nv_bfloat16* ol = (z < 2) ? (qkl + (size_t)z * BH * SEQ * DEP) : vtl;

    constexpr uint32_t AOFF = 0, ABUF = 65536;        // hi@0 lo@32768, x2
    constexpr uint32_t BOFF = 131072, BBUF = 32768;   // hi@0 lo@16384, x2
    const int warpM = (wid >> 1) * 64, warpN = (wid & 1) * 64;

    uint32_t a_sw[4], b_sw[4];
    lane_sw(lane, a_sw, b_sw);

    float acc[4][8][4];
    #pragma unroll
    for (int i = 0; i < 4; i++)
        #pragma unroll
        for (int j = 0; j < 8; j++)
            #pragma unroll
            for (int r = 0; r < 4; r++) acc[i][j][r] = 0.f;

    auto issueAB = [&](int c, int buf) {
        const int k0 = c << 6;
        #pragma unroll
        for (int i = 0; i < 8; i++) {
            int u = tid + i * 256, row = u >> 3, c8 = u & 7;
            uint32_t d = swz((uint32_t)row * 128 + c8 * 16);
            const size_t src = (size_t)(bm + row) * DM + k0 + c8 * 8;
            CP16(sb + AOFF + buf * ABUF + d,         Ah + src);
            CP16(sb + AOFF + buf * ABUF + 32768 + d, Al + src);
        }
        #pragma unroll
        for (int i = 0; i < 4; i++) {
            int u = tid + i * 256, row = u >> 3, c8 = u & 7;
            uint32_t d = swz((uint32_t)row * 128 + c8 * 16);
            const size_t src = (size_t)(bn + row) * DM + k0 + c8 * 8;
            CP16(sb + BOFF + buf * BBUF + d,         Bh + src);
            CP16(sb + BOFF + buf * BBUF + 16384 + d, Bl + src);
        }
        CP_COMMIT();
    };

    const int C = DM >> 6;  // 16
    issueAB(0, 0);
    for (int c = 0; c < C; c++) {
        CP_WAIT(0);
        __syncthreads();
        if (c + 1 < C) issueAB(c + 1, (c + 1) & 1);
        compute_chunk<4, 8>(sb + AOFF + (c & 1) * ABUF,
                            sb + AOFF + (c & 1) * ABUF + 32768,
                            sb + BOFF + (c & 1) * BBUF,
                            sb + BOFF + (c & 1) * BBUF + 16384,
                            warpM, warpN, a_sw, b_sw, acc);
    }

    // epilogue
    const int rr = lane >> 2, cc = (lane & 3) * 2;
    #pragma unroll
    for (int mf = 0; mf < 4; mf++)
        #pragma unroll
        for (int nf = 0; nf < 8; nf++) {
            const int n = bn + warpN + nf * 8 + cc;
            #pragma unroll
            for (int half = 0; half < 2; half++) {
                const int m = bm + warpM + mf * 16 + rr + half * 8;
                const float x = acc[mf][nf][half*2]     + bias[n];
                const float y = acc[mf][nf][half*2 + 1] + bias[n + 1];
                const int b = m >> 11, l = m & 2047;
                if (z < 2) {  // head layout [bh][l][d]
                    const int h = n >> 6, d = n & 63;
                    const size_t o = ((size_t)(b * NH + h) * SEQ + l) * DEP + d;
                    const float hx = __bfloat162float(__float2bfloat16(x));
                    const float hy = __bfloat162float(__float2bfloat16(y));
                    *(uint32_t*)(oh + o) = pack_bf2(x, y);
                    *(uint32_t*)(ol + o) = pack_bf2(x - hx, y - hy);
                } else {      // V transposed [bh][d][l]
                    #pragma unroll
                    for (int j = 0; j < 2; j++) {
                        const int nn = n + j;
                        const int h = nn >> 6, d = nn & 63;
                        const float v = j ? y : x;
                        const __nv_bfloat16 hv = __float2bfloat16(v);
                        const size_t o = ((size_t)(b * NH + h) * DEP + d) * SEQ + l;
                        oh[o] = hv;
                        ol[o] = __float2bfloat16(v - __bfloat162float(hv));
                    }
                }
            }
        }
}

// ---------------------------------------------------------------------------
// Scores: CTA 128x128, 128 threads (2 warps... 4 warps of 64x64) -> 2 CTAs/SM.
// Single-shot K=64. bf16 mask bias. Writes raw masked S fp32 + partials.
// ---------------------------------------------------------------------------
__global__ void __launch_bounds__(128, 2)
gemm_scores(const __nv_bfloat16* __restrict__ Ahi, const __nv_bfloat16* __restrict__ Alo,
            const __nv_bfloat16* __restrict__ Bhi, const __nv_bfloat16* __restrict__ Blo,
            const __nv_bfloat16* __restrict__ maskb, float* __restrict__ S,
            float* __restrict__ pmax, float* __restrict__ psum)
{
    extern __shared__ char smem[];
    const uint32_t sb = smem_u32(smem);
    const int tid = threadIdx.x, lane = tid & 31, wid = tid >> 5;
    const int bn = blockIdx.x * 128, bm = blockIdx.y * 128, z = blockIdx.z;

    const __nv_bfloat16* Ah = Ahi + (size_t)z * SEQ * DEP;
    const __nv_bfloat16* Al = Alo + (size_t)z * SEQ * DEP;
    const __nv_bfloat16* Bh = Bhi + (size_t)z * SEQ * DEP;
    const __nv_bfloat16* Bl = Blo + (size_t)z * SEQ * DEP;

    const int warpM = (wid >> 1) * 64, warpN = (wid & 1) * 64;
    uint32_t a_sw[4], b_sw[4];
    lane_sw(lane, a_sw, b_sw);

    // A hi@0 lo@16384; B hi@32768 lo@49152
    #pragma unroll
    for (int i = 0; i < 8; i++) {
        int u = tid + i * 128, row = u >> 3, c8 = u & 7;
        uint32_t d = swz((uint32_t)row * 128 + c8 * 16);
        const size_t sa = (size_t)(bm + row) * DEP + c8 * 8;
        const size_t sbo = (size_t)(bn + row) * DEP + c8 * 8;
        CP16(sb + d,         Ah + sa);
        CP16(sb + 16384 + d, Al + sa);
        CP16(sb + 32768 + d, Bh + sbo);
        CP16(sb + 49152 + d, Bl + sbo);
    }
    CP_COMMIT();
    CP_WAIT(0);
    __syncthreads();

    float acc[4][8][4];
    #pragma unroll
    for (int i = 0; i < 4; i++)
        #pragma unroll
        for (int j = 0; j < 8; j++)
            #pragma unroll
            for (int r = 0; r < 4; r++) acc[i][j][r] = 0.f;

    compute_chunk<4, 8>(sb, sb + 16384, sb + 32768, sb + 49152,
                        warpM, warpN, a_sw, b_sw, acc);

    // scale + mask, write S, accumulate partials
    const int rr = lane >> 2, cc = (lane & 3) * 2;
    float* smax = (float*)(smem + 65536);   // [2][128]
    float* ssum = smax + 256;               // [2][128]

    #pragma unroll
    for (int mf = 0; mf < 4; mf++)
        #pragma unroll
        for (int half = 0; half < 2; half++) {
            const int r = warpM + mf * 16 + rr + half * 8;
            const int m = bm + r;
            const __nv_bfloat16* mrow = maskb + ((size_t)(z >> 4) * SEQ + m) * SEQ;
            float mx = -3.4e38f;
            #pragma unroll
            for (int nf = 0; nf < 8; nf++) {
                const int n = bn + warpN + nf * 8 + cc;
                uint32_t mraw = *(const uint32_t*)(mrow + n);
                __nv_bfloat162 mv = *(__nv_bfloat162*)&mraw;
                float x = acc[mf][nf][half*2]     * 0.125f + __bfloat162float(mv.x);
                float y = acc[mf][nf][half*2 + 1] * 0.125f + __bfloat162float(mv.y);
                acc[mf][nf][half*2] = x; acc[mf][nf][half*2+1] = y;
                float2 v = {x, y};
                *(float2*)(S + ((size_t)z * SEQ + m) * SEQ + n) = v;
                mx = fmaxf(mx, fmaxf(x, y));
            }
            mx = fmaxf(mx, __shfl_xor_sync(0xffffffffu, mx, 1));
            mx = fmaxf(mx, __shfl_xor_sync(0xffffffffu, mx, 2));
            float sm = 0.f;
            #pragma unroll
            for (int nf = 0; nf < 8; nf++) {
                sm += __expf(acc[mf][nf][half*2]   - mx);
                sm += __expf(acc[mf][nf][half*2+1] - mx);
            }
            sm += __shfl_xor_sync(0xffffffffu, sm, 1);
            sm += __shfl_xor_sync(0xffffffffu, sm, 2);
            if ((lane & 3) == 0) {
                smax[(wid & 1) * 128 + r] = mx;
                ssum[(wid & 1) * 128 + r] = sm;
            }
        }
    __syncthreads();
    {
        float m0 = smax[tid], m1 = smax[128 + tid];
        float M = fmaxf(m0, m1);
        float Zp = ssum[tid] * __expf(m0 - M) + ssum[128 + tid] * __expf(m1 - M);
        const size_t o = ((size_t)z * 16 + blockIdx.x) * SEQ + bm + tid;
        pmax[o] = M;
        psum[o] = Zp;
    }
}

// ---------------------------------------------------------------------------
// Combine partials (16 tiles) -> row max M and invZ
// ---------------------------------------------------------------------------
__global__ void __launch_bounds__(256)
combine_kernel(const float* __restrict__ pmax, const float* __restrict__ psum,
               float* __restrict__ gM, float* __restrict__ gInvZ)
{
    const int R = blockIdx.x * 256 + threadIdx.x;   // 0..65535
    const int bh = R >> 11, m = R & 2047;
    float mx[16];
    float M = -3.4e38f;
    #pragma unroll
    for (int t = 0; t < 16; t++) {
        mx[t] = pmax[((size_t)bh * 16 + t) * SEQ + m];
        M = fmaxf(M, mx[t]);
    }
    float Z = 0.f;
    #pragma unroll
    for (int t = 0; t < 16; t++)
        Z += psum[((size_t)bh * 16 + t) * SEQ + m] * __expf(mx[t] - M);
    gM[R] = M;
    gInvZ[R] = 1.0f / Z;
}

// ---------------------------------------------------------------------------
// AV: CTA 256x64, warp 64x32 (MF=4, NF=4). A = raw S fp32 -> finalize
// w = exp(s-M)*invZ (write in place), split hi/lo, MMA vs pre-split V^T.
// ---------------------------------------------------------------------------
__global__ void __launch_bounds__(256, 1)
gemm_av(float* __restrict__ S,
        const __nv_bfloat16* __restrict__ Bhi, const __nv_bfloat16* __restrict__ Blo,
        const float* __restrict__ gM, const float* __restrict__ gInvZ,
        __nv_bfloat16* __restrict__ oh, __nv_bfloat16* __restrict__ ol)
{
    extern __shared__ char smem[];
    const uint32_t sb = smem_u32(smem);
    const int tid = threadIdx.x, lane = tid & 31, wid = tid >> 5;
    const int bm = blockIdx.y * 256, z = blockIdx.z;

    float* Sp = S + (size_t)z * SEQ * SEQ;
    const __nv_bfloat16* Bh = Bhi + (size_t)z * DEP * SEQ;
    const __nv_bfloat16* Bl = Blo + (size_t)z * DEP * SEQ;
    const int Rbase = z * SEQ + bm;

    constexpr uint32_t AOFF = 0, ABUF = 65536;      // hi@0 lo@32768, x2
    constexpr uint32_t BOFF = 131072, BBUF = 16384; // hi@0 lo@8192, x3
    const int warpM = (wid >> 1) * 64, warpN = (wid & 1) * 32;

    uint32_t a_sw[4], b_sw[4];
    lane_sw(lane, a_sw, b_sw);

    float acc[4][4][4];
    #pragma unroll
    for (int i = 0; i < 4; i++)
        #pragma unroll
        for (int j = 0; j < 4; j++)
            #pragma unroll
            for (int r = 0; r < 4; r++) acc[i][j][r] = 0.f;

    float4 sv[16];
    auto ldgA = [&](int c) {
        const int k0 = c << 6;
        #pragma unroll
        for (int j = 0; j < 16; j++) {
            int g = j * 256 + tid, row = g >> 4, c4 = g & 15;
            sv[j] = *(const float4*)(Sp + (size_t)(bm + row) * SEQ + k0 + c4 * 4);
        }
    };
    auto convA = [&](int c, int buf) {
        const int k0 = c << 6;
        #pragma unroll
        for (int j = 0; j < 16; j++) {
            int g = j * 256 + tid, row = g >> 4, c4 = g & 15;
            const float M = gM[Rbase + row], iZ = gInvZ[Rbase + row];
            float vv[4];
            vv[0] = __expf(sv[j].x - M) * iZ;
            vv[1] = __expf(sv[j].y - M) * iZ;
            vv[2] = __expf(sv[j].z - M) * iZ;
            vv[3] = __expf(sv[j].w - M) * iZ;
            *(float4*)(Sp + (size_t)(bm + row) * SEQ + k0 + c4 * 4) =
                make_float4(vv[0], vv[1], vv[2], vv[3]);
            float h[4];
            #pragma unroll
            for (int t = 0; t < 4; t++) h[t] = __bfloat162float(__float2bfloat16(vv[t]));
            uint2 H = { pack_bf2(vv[0], vv[1]), pack_bf2(vv[2], vv[3]) };
            uint2 L = { pack_bf2(vv[0]-h[0], vv[1]-h[1]), pack_bf2(vv[2]-h[2], vv[3]-h[3]) };
            uint32_t d = swz((uint32_t)row * 128 + c4 * 8);
            *(uint2*)(smem + AOFF + buf * ABUF + d)         = H;
            *(uint2*)(smem + AOFF + buf * ABUF + 32768 + d) = L;
        }
    };
    auto issueB = [&](int c, int buf) {
        const int k0 = c << 6;
        #pragma unroll
        for (int i = 0; i < 2; i++) {
            int u = tid + i * 256, row = u >> 3, c8 = u & 7;
            uint32_t d = swz((uint32_t)row * 128 + c8 * 16);
            const size_t src = (size_t)row * SEQ + k0 + c8 * 8;
            CP16(sb + BOFF + buf * BBUF + d,        Bh + src);
            CP16(sb + BOFF + buf * BBUF + 8192 + d, Bl + src);
        }
        CP_COMMIT();
    };

    const int C = SEQ >> 6;  // 32
    ldgA(0);
    issueB(0, 0);
    issueB(1, 1);
    convA(0, 0);
    ldgA(1);
    for (int c = 0; c < C; c++) {
        if (c + 1 < C) CP_WAIT(1); else CP_WAIT(0);
        __syncthreads();
        if (c + 2 < C) issueB(c + 2, (c + 2) % 3);
        compute_chunk<4, 4>(sb + AOFF + (c & 1) * ABUF,
                            sb + AOFF + (c & 1) * ABUF + 32768,
                            sb + BOFF + (c % 3) * BBUF,
                            sb + BOFF + (c % 3) * BBUF + 8192,
                            warpM, warpN, a_sw, b_sw, acc);
        if (c + 1 < C) {
            convA(c + 1, (c + 1) & 1);
            if (c + 2 < C) ldgA(c + 2);
        }
    }

    // epilogue -> at hi/lo [b*SEQ+m][h*DEP+n]
    const int rr = lane >> 2, cc = (lane & 3) * 2;
    #pragma unroll
    for (int mf = 0; mf < 4; mf++)
        #pragma unroll
        for (int nf = 0; nf < 4; nf++) {
            const int n = warpN + nf * 8 + cc;
            #pragma unroll
            for (int half = 0; half < 2; half++) {
                const int m = bm + warpM + mf * 16 + rr + half * 8;
                const float x = acc[mf][nf][half*2];
                const float y = acc[mf][nf][half*2+1];
                const size_t o = ((size_t)((z >> 4) * SEQ + m)) * DM + (z & 15) * DEP + n;
                const float hx = __bfloat162float(__float2bfloat16(x));
                const float hy = __bfloat162float(__float2bfloat16(y));
                *(uint32_t*)(oh + o) = pack_bf2(x, y);
                *(uint32_t*)(ol + o) = pack_bf2(x - hx, y - hy);
            }
        }
}

// ---------------------------------------------------------------------------
// Output projection: CTA 256x128, warp 64x64, pre-split A and B.
// ---------------------------------------------------------------------------
__global__ void __launch_bounds__(256, 1)
gemm_out(const __nv_bfloat16* __restrict__ Ahi, const __nv_bfloat16* __restrict__ Alo,
         const __nv_bfloat16* __restrict__ Bhi, const __nv_bfloat16* __restrict__ Blo,
         const float* __restrict__ bias, float* __restrict__ outf)
{
    extern __shared__ char smem[];
    const uint32_t sb = smem_u32(smem);
    const int tid = threadIdx.x, lane = tid & 31, wid = tid >> 5;
    const int bn = blockIdx.x * 128, bm = blockIdx.y * 256;

    constexpr uint32_t AOFF = 0, ABUF = 65536;        // hi@0 lo@32768, x2
    constexpr uint32_t BOFF = 131072, BBUF = 32768;   // hi@0 lo@16384, x2
    const int warpM = (wid >> 1) * 64, warpN = (wid & 1) * 64;

    uint32_t a_sw[4], b_sw[4];
    lane_sw(lane, a_sw, b_sw);

    float acc[4][8][4];
    #pragma unroll
    for (int i = 0; i < 4; i++)
        #pragma unroll
        for (int j = 0; j < 8; j++)
            #pragma unroll
            for (int r = 0; r < 4; r++) acc[i][j][r] = 0.f;

    auto issueAB = [&](int c, int buf) {
        const int k0 = c << 6;
        #pragma unroll
        for (int i = 0; i < 8; i++) {
            int u = tid + i * 256, row = u >> 3, c8 = u & 7;
            uint32_t d = swz((uint32_t)row * 128 + c8 * 16);
            const size_t src = (size_t)(bm + row) * DM + k0 + c8 * 8;
            CP16(sb + AOFF + buf * ABUF + d,         Ahi + src);
            CP16(sb + AOFF + buf * ABUF + 32768 + d, Alo + src);
        }
        #pragma unroll
        for (int i = 0; i < 4; i++) {
            int u = tid + i * 256, row = u >> 3, c8 = u & 7;
            uint32_t d = swz((uint32_t)row * 128 + c8 * 16);
            const size_t src = (size_t)(bn + row) * DM + k0 + c8 * 8;
            CP16(sb + BOFF + buf * BBUF + d,         Bhi + src);
            CP16(sb + BOFF + buf * BBUF + 16384 + d, Blo + src);
        }
        CP_COMMIT();
    };

    const int C = DM >> 6;  // 16
    issueAB(0, 0);
    for (int c = 0; c < C; c++) {
        CP_WAIT(0);
        __syncthreads();
        if (c + 1 < C) issueAB(c + 1, (c + 1) & 1);
        compute_chunk<4, 8>(sb + AOFF + (c & 1) * ABUF,
                            sb + AOFF + (c & 1) * ABUF + 32768,
                            sb + BOFF + (c & 1) * BBUF,
                            sb + BOFF + (c & 1) * BBUF + 16384,
                            warpM, warpN, a_sw, b_sw, acc);
    }

    const int rr = lane >> 2, cc = (lane & 3) * 2;
    #pragma unroll
    for (int mf = 0; mf < 4; mf++)
        #pragma unroll
        for (int nf = 0; nf < 8; nf++) {
            const int n = bn + warpN + nf * 8 + cc;
            #pragma unroll
            for (int half = 0; half < 2; half++) {
                const int m = bm + warpM + mf * 16 + rr + half * 8;
                float2 v = { acc[mf][nf][half*2] + bias[n],
                             acc[mf][nf][half*2+1] + bias[n+1] };
                *(float2*)(outf + (size_t)m * DM + n) = v;
            }
        }
}

// ---------------------------------------------------------------------------
extern "C" void kernel_launch(void* const* d_in, const int* in_sizes, int n_in,
                              void* d_out, int out_size)
{
    const float* q    = (const float*)d_in[0];
    const float* k    = (const float*)d_in[1];
    const float* v    = (const float*)d_in[2];
    const int*   mask = (const int*)  d_in[3];
    const float* Wq   = (const float*)d_in[4];
    const float* bq   = (const float*)d_in[5];
    const float* Wk   = (const float*)d_in[6];
    const float* bk   = (const float*)d_in[7];
    const float* Wv   = (const float*)d_in[8];
    const float* bv   = (const float*)d_in[9];
    const float* Wo   = (const float*)d_in[10];
    const float* bo   = (const float*)d_in[11];

    float* out   = (float*)d_out;
    float* attnW = out + (size_t)MTOT * DM;

    __nv_bfloat16 *xh,*xl,*wqkvh,*wqkvl,*woh,*wol;
    __nv_bfloat16 *qkh,*qkl,*vth,*vtl,*ath,*atl,*maskb;
    float *b3,*pmax,*psum,*gM,*gZ;
    cudaGetSymbolAddress((void**)&xh, g_x_hi);        cudaGetSymbolAddress((void**)&xl, g_x_lo);
    cudaGetSymbolAddress((void**)&wqkvh, g_wqkv_hi);  cudaGetSymbolAddress((void**)&wqkvl, g_wqkv_lo);
    cudaGetSymbolAddress((void**)&woh, g_wo_hi);      cudaGetSymbolAddress((void**)&wol, g_wo_lo);
    cudaGetSymbolAddress((void**)&qkh, g_qkh_hi);     cudaGetSymbolAddress((void**)&qkl, g_qkh_lo);
    cudaGetSymbolAddress((void**)&vth, g_vt_hi);      cudaGetSymbolAddress((void**)&vtl, g_vt_lo);
    cudaGetSymbolAddress((void**)&ath, g_at_hi);      cudaGetSymbolAddress((void**)&atl, g_at_lo);
    cudaGetSymbolAddress((void**)&maskb, g_maskb);
    cudaGetSymbolAddress((void**)&b3, g_bias3);
    cudaGetSymbolAddress((void**)&pmax, g_pmax);      cudaGetSymbolAddress((void**)&psum, g_psum);
    cudaGetSymbolAddress((void**)&gM, g_M);           cudaGetSymbolAddress((void**)&gZ, g_invZ);

    __nv_bfloat16* qhh = qkh;
    __nv_bfloat16* qhl = qkl;
    __nv_bfloat16* khh = qkh + (size_t)BH * SEQ * DEP;
    __nv_bfloat16* khl = qkl + (size_t)BH * SEQ * DEP;

    const int SM_BIG = 2 * 65536 + 2 * 32768;       // 196608
    const int SM_SC  = 65536 + 2048;                // 67584
    const int SM_AV  = 2 * 65536 + 3 * 16384;       // 180224
    cudaFuncSetAttribute(gemm_proj,   cudaFuncAttributeMaxDynamicSharedMemorySize, SM_BIG);
    cudaFuncSetAttribute(gemm_scores, cudaFuncAttributeMaxDynamicSharedMemorySize, SM_SC);
    cudaFuncSetAttribute(gemm_av,     cudaFuncAttributeMaxDynamicSharedMemorySize, SM_AV);
    cudaFuncSetAttribute(gemm_out,    cudaFuncAttributeMaxDynamicSharedMemorySize, SM_BIG);

    // 1. input splits + mask/bias prep + weight transpose/splits
    split4_kernel<<<dim3(MTOT * DM / 4 / 256, 1, 3), 256>>>(q, k, v, xh, xl);
    mask_prep_kernel<<<2u * SEQ * SEQ / 4 / 256, 256>>>(mask, maskb, bq, bk, bv, b3);
    transpose_split_kernel<<<dim3(32, 32, 4), dim3(32, 8)>>>(
        Wq, Wk, Wv, Wo, wqkvh, wqkvl, woh, wol);

    // 2. Q/K/V projections (consolidated pointers)
    gemm_proj<<<dim3(8, 16, 3), 256, SM_BIG>>>(
        xh, xl, wqkvh, wqkvl, b3, qkh, qkl, vth, vtl);

    // 3. scores + mask + softmax partials (128-thread CTAs, 2/SM)
    gemm_scores<<<dim3(16, 16, BH), 128, SM_SC>>>(
        qhh, qhl, khh, khl, maskb, attnW, pmax, psum);

    // 4. combine partials
    combine_kernel<<<BH * SEQ / 256, 256>>>(pmax, psum, gM, gZ);

    // 5. AV with fused softmax finalize (CTA 256x64)
    gemm_av<<<dim3(1, 8, BH), 256, SM_AV>>>(
        attnW, vth, vtl, gM, gZ, ath, atl);

    // 6. output projection
    gemm_out<<<dim3(8, 16, 1), 256, SM_BIG>>>(ath, atl, woh, wol, bo, out);
}